// round 13
// baseline (speedup 1.0000x reference)
#include <cuda_runtime.h>
#include <cuda_bf16.h>
#include <stdint.h>
#include <math.h>

// ---------------------------------------------------------------------------
// Scratch. __device__ globals zero-init; halo rings never written -> stay 0.
// Activations: channel-pair packed bf16, h+m interleaved:
// uint2 { .x = bf16x2 hi, .y = bf16x2 residual }, layout [B][C/2][(H+2)*(W+2)].
// ---------------------------------------------------------------------------
__device__ float g_A[64 * 64 * 64 * 64];   // fp32 scratch
__device__ float g_B[64 * 128 * 32 * 32];  // fp32 scratch

__device__ uint2 gT1[64 * 32  * 34 * 34];
__device__ uint2 gT2[64 * 64  * 18 * 18];
__device__ uint2 gT3[64 * 128 * 18 * 18];
__device__ uint2 gT4[64 * 128 * 10 * 10];
__device__ uint2 gT5[64 * 256 * 10 * 10];
__device__ uint2 gT6[64 * 256 * 6 * 6];
__device__ uint2 gT7[64 * 256 * 6 * 6];

// Weights: ldmatrix-ready layout, h and m separate arrays.
// per (cogrp=CO/32, slice=CI/16, kj): 256 words = 2 mt * 4 mats * 8 rows * 4 words
__device__ uint32_t g_WH[4608000], g_WM[4608000];
#define WOFF_C1  0
#define WOFF_C2A 36864
#define WOFF_C2B 184320
#define WOFF_C3A 479232
#define WOFF_C3B 1069056
#define WOFF_C4A 2248704
#define WOFF_C4B 3428352

// ---------------------------------------------------------------------------
// helpers
// ---------------------------------------------------------------------------
__device__ __forceinline__ uint32_t packbf2(float lo, float hi) {
    uint32_t r;
    asm("cvt.rn.bf16x2.f32 %0, %1, %2;" : "=r"(r) : "f"(hi), "f"(lo));
    return r;
}
__device__ __forceinline__ void mma_bf16(float* d,
                                         uint32_t a0, uint32_t a1, uint32_t a2, uint32_t a3,
                                         uint32_t b0, uint32_t b1) {
    asm volatile(
        "mma.sync.aligned.m16n8k16.row.col.f32.bf16.bf16.f32 "
        "{%0,%1,%2,%3}, {%4,%5,%6,%7}, {%8,%9}, {%0,%1,%2,%3};"
        : "+f"(d[0]), "+f"(d[1]), "+f"(d[2]), "+f"(d[3])
        : "r"(a0), "r"(a1), "r"(a2), "r"(a3), "r"(b0), "r"(b1));
}
__device__ __forceinline__ void ldsm_x4(uint32_t* r, uint32_t addr) {
    asm volatile("ldmatrix.sync.aligned.m8n8.x4.shared.b16 {%0,%1,%2,%3}, [%4];"
        : "=r"(r[0]), "=r"(r[1]), "=r"(r[2]), "=r"(r[3]) : "r"(addr));
}
__device__ __forceinline__ void cp16(uint32_t dst, const void* src) {
    asm volatile("cp.async.cg.shared.global [%0], [%1], 16;" :: "r"(dst), "l"(src));
}

// ---------------------------------------------------------------------------
// Weight prep: fp32 OIHW -> ldmatrix-layout h/m arrays.
// word = ((cogrp*NSL + sl)*9 + kj)*256 + mt*128 + mat*32 + (m%8)*4 + (pc&3)
// ---------------------------------------------------------------------------
__global__ void prep_w_all(const float* __restrict__ w1, const float* __restrict__ w2a,
                           const float* __restrict__ w2b, const float* __restrict__ w3a,
                           const float* __restrict__ w3b, const float* __restrict__ w4a,
                           const float* __restrict__ w4b)
{
    int i = blockIdx.x * blockDim.x + threadIdx.x;
    const float* src; int CI; int woffl; int base;
    if      (i < 36864)   { src = w1;  CI = 64;  woffl = WOFF_C1;  base = 0; }
    else if (i < 184320)  { src = w2a; CI = 128; woffl = WOFF_C2A; base = 36864; }
    else if (i < 479232)  { src = w2b; CI = 256; woffl = WOFF_C2B; base = 184320; }
    else if (i < 1069056) { src = w3a; CI = 256; woffl = WOFF_C3A; base = 479232; }
    else if (i < 2248704) { src = w3b; CI = 512; woffl = WOFF_C3B; base = 1069056; }
    else if (i < 3428352) { src = w4a; CI = 512; woffl = WOFF_C4A; base = 2248704; }
    else if (i < 4608000) { src = w4b; CI = 512; woffl = WOFF_C4B; base = 3428352; }
    else return;
    int j  = i - base;
    int seg = (CI / 2) * 9;
    int co = j / seg;
    int r  = j % seg;
    int pcg = r / 9, kj = r % 9;
    int sl = pcg >> 3, pc = pcg & 7;
    float v0 = src[((size_t)co * CI + 2 * pcg) * 9 + kj];
    float v1 = src[((size_t)co * CI + 2 * pcg + 1) * 9 + kj];
    float h0 = __bfloat162float(__float2bfloat16(v0));
    float h1 = __bfloat162float(__float2bfloat16(v1));
    int mt = (co >> 4) & 1, m = co & 15;
    int mat = (pc < 4) ? ((m < 8) ? 0 : 1) : ((m < 8) ? 2 : 3);
    int NSL = CI / 16;
    size_t word = (size_t)woffl
                + ((((size_t)(co >> 5) * NSL + sl) * 9 + kj) * 256)
                + mt * 128 + mat * 32 + (m & 7) * 4 + (pc & 3);
    g_WH[word] = packbf2(h0, h1);
    g_WM[word] = packbf2(v0 - h0, v1 - h1);
}

// ---------------------------------------------------------------------------
// Implicit-GEMM conv3x3 SAME + bias + ReLU via bf16x2 (3-product) mma k16.
// 256 thr = 8 N-warps; CO tile 32 (2 m16/warp); 16 channels per K-slice.
// A-frags via ldmatrix.x4; B via LDS.64 (h/m interleaved); cp.async 2-stage.
// ---------------------------------------------------------------------------
template <int H, int W, int CI, int CO, int NB, int NROW, bool OUT_SPLIT>
__global__ void __launch_bounds__(256, 2)
conv_bf16(const uint2* __restrict__ inHM,
          const uint32_t* __restrict__ wH, const uint32_t* __restrict__ wM,
          const float* __restrict__ bias, float* __restrict__ outF,
          uint2* __restrict__ outHM)
{
    constexpr int WP = W + 2, HP = H + 2;
    constexpr int SP2 = W + 2;
    constexpr int GP = HP * WP;             // global plane (uint2)
    constexpr int SLS = (NROW + 2) * SP2;   // staged plane (uint2), ≡4 mod 16
    constexpr int BN = NB * NROW * W;
    constexpr int WN = BN / 8;
    constexpr int NC = WN / 8;
    constexpr int SIN2 = NB * 8 * SLS;      // uint2 per input buffer
    constexpr int NCHI = SLS / 2;           // 16B chunks per (im,pc)
    constexpr int TCHI = NB * 8 * NCHI;
    constexpr int NSLICE = CI / 16;

    extern __shared__ uint32_t smu[];
    uint2* sIn[2] = { (uint2*)smu, (uint2*)smu + SIN2 };
    uint32_t* wbuf = smu + 4 * SIN2;        // 4 x 2304 words: H0,H1,M0,M1

    const int tid = threadIdx.x, warp = tid >> 5, lane = tid & 31;
    const int kk = lane & 3, ng = lane >> 2, wn = warp;
    const int ty0 = blockIdx.x * NROW;
    const int oc0 = blockIdx.y * 32;
    const int b0  = blockIdx.z * NB;

    const uint32_t inS0 = (uint32_t)__cvta_generic_to_shared(sIn[0]);
    const uint32_t inS1 = (uint32_t)__cvta_generic_to_shared(sIn[1]);
    const uint32_t wS   = (uint32_t)__cvta_generic_to_shared(wbuf);
    // byte offsets of the 4 weight buffers
    const uint32_t wHS[2] = { wS, wS + 2304 * 4 };
    const uint32_t wMS[2] = { wS + 4608 * 4, wS + 6912 * 4 };

    int boff[NC];
#pragma unroll
    for (int ch = 0; ch < NC; ch++) {
        int n = wn * WN + ch * 8 + ng;
        int x = n % W; int t = n / W;
        int yy = t % NROW; int im = t / NROW;
        boff[ch] = (im * 8 + kk) * SLS + yy * SP2 + x;
    }

    float acc[2][NC][4];
#pragma unroll
    for (int mt = 0; mt < 2; mt++)
#pragma unroll
        for (int ch = 0; ch < NC; ch++)
#pragma unroll
            for (int j = 0; j < 4; j++) acc[mt][ch][j] = 0.f;

    auto stage = [&](int sl, int bufi) {
        uint32_t dI = bufi ? inS1 : inS0;
        for (int i = tid; i < TCHI; i += 256) {
            int c = i % NCHI; int t = i / NCHI;
            int pc = t % 8; int im = t / 8;
            size_t gbase = ((size_t)(b0 + im) * (CI / 2) + sl * 8 + pc) * GP
                         + (size_t)ty0 * WP + 2 * c;
            cp16(dI + (uint32_t)(((im * 8 + pc) * SLS + 2 * c) * 8), inHM + gbase);
        }
        size_t wbase = ((size_t)blockIdx.y * NSLICE + sl) * 2304;
        uint32_t dH = wHS[bufi], dM = wMS[bufi];
        for (int i = tid; i < 576; i += 256) {
            cp16(dH + (uint32_t)(i * 16), wH + wbase + 4 * i);
            cp16(dM + (uint32_t)(i * 16), wM + wbase + 4 * i);
        }
        asm volatile("cp.async.commit_group;" ::: "memory");
    };

    stage(0, 0);
    for (int s = 0; s < NSLICE; s++) {
        if (s + 1 < NSLICE) {
            stage(s + 1, (s + 1) & 1);
            asm volatile("cp.async.wait_group 1;" ::: "memory");
        } else {
            asm volatile("cp.async.wait_group 0;" ::: "memory");
        }
        __syncthreads();

        const uint2* si = sIn[s & 1];
        const uint32_t aHb = wHS[s & 1] + lane * 16;
        const uint32_t aMb = wMS[s & 1] + lane * 16;
#pragma unroll 3
        for (int kj = 0; kj < 9; kj++) {
            const int kyx = (kj / 3) * SP2 + (kj % 3);
            uint32_t ah[2][4], am[2][4];
            ldsm_x4(ah[0], aHb + kj * 1024);
            ldsm_x4(ah[1], aHb + kj * 1024 + 512);
            ldsm_x4(am[0], aMb + kj * 1024);
            ldsm_x4(am[1], aMb + kj * 1024 + 512);

            uint32_t bh[NC][2], bm[NC][2];
#pragma unroll
            for (int ch = 0; ch < NC; ch++) {
                uint2 v0 = si[boff[ch] + kyx];
                uint2 v1 = si[boff[ch] + kyx + 4 * SLS];
                bh[ch][0] = v0.x; bh[ch][1] = v1.x;
                bm[ch][0] = v0.y; bm[ch][1] = v1.y;
            }
            // pass 1: h*h
#pragma unroll
            for (int ch = 0; ch < NC; ch++)
#pragma unroll
                for (int mt = 0; mt < 2; mt++)
                    mma_bf16(acc[mt][ch], ah[mt][0], ah[mt][1], ah[mt][2], ah[mt][3],
                             bh[ch][0], bh[ch][1]);
            // pass 2: h_w * m_x
#pragma unroll
            for (int ch = 0; ch < NC; ch++)
#pragma unroll
                for (int mt = 0; mt < 2; mt++)
                    mma_bf16(acc[mt][ch], ah[mt][0], ah[mt][1], ah[mt][2], ah[mt][3],
                             bm[ch][0], bm[ch][1]);
            // pass 3: m_w * h_x
#pragma unroll
            for (int ch = 0; ch < NC; ch++)
#pragma unroll
                for (int mt = 0; mt < 2; mt++)
                    mma_bf16(acc[mt][ch], am[mt][0], am[mt][1], am[mt][2], am[mt][3],
                             bh[ch][0], bh[ch][1]);
        }
        __syncthreads();
    }

    // epilogue
#pragma unroll
    for (int mt = 0; mt < 2; mt++) {
        const int co = oc0 + mt * 16 + ng;
        const float bva = bias[co];
        const float bvb = bias[co + 8];
#pragma unroll
        for (int ch = 0; ch < NC; ch++) {
#pragma unroll
            for (int j = 0; j < 2; j++) {
                int n = wn * WN + ch * 8 + kk * 2 + j;
                int x = n % W; int t = n / W;
                int yy = t % NROW; int im = t / NROW;
                float v0 = fmaxf(acc[mt][ch][j] + bva, 0.f);
                float v1 = fmaxf(acc[mt][ch][j + 2] + bvb, 0.f);
                if constexpr (OUT_SPLIT) {
                    // channel co -> pair co>>1, half co&1
                    size_t w0 = ((size_t)(b0 + im) * (CO / 2) + (co >> 1)) * GP
                              + (size_t)(ty0 + yy + 1) * WP + (x + 1);
                    __nv_bfloat16* p0 = (__nv_bfloat16*)(outHM + w0);
                    __nv_bfloat16 hb0 = __float2bfloat16(v0);
                    p0[co & 1] = hb0;
                    p0[2 + (co & 1)] = __float2bfloat16(v0 - __bfloat162float(hb0));
                    int co1 = co + 8;
                    size_t w1 = ((size_t)(b0 + im) * (CO / 2) + (co1 >> 1)) * GP
                              + (size_t)(ty0 + yy + 1) * WP + (x + 1);
                    __nv_bfloat16* p1 = (__nv_bfloat16*)(outHM + w1);
                    __nv_bfloat16 hb1 = __float2bfloat16(v1);
                    p1[co1 & 1] = hb1;
                    p1[2 + (co1 & 1)] = __float2bfloat16(v1 - __bfloat162float(hb1));
                } else {
                    size_t base = (((size_t)(b0 + im) * CO + co) * H + (ty0 + yy)) * W + x;
                    outF[base] = v0;
                    outF[base + (size_t)8 * H * W] = v1;
                }
            }
        }
    }
}

// ---------------------------------------------------------------------------
// conv0: direct fp32 3->64 @64x64, fused pool, writes packed interleaved T1.
// ---------------------------------------------------------------------------
__global__ void __launch_bounds__(256)
conv0_k(const float* __restrict__ in, const float* __restrict__ wt,
        const float* __restrict__ bias, uint2* __restrict__ outT)
{
    constexpr int H = 64, W = 64, CI = 3, CO = 64;
    constexpr int TPH = 16, TPW = 16, RPH = 4, RPW = 4, OCT = 64, RC = 4;
    constexpr int NPXW = TPW / RPW;
    constexpr int NPX  = (TPH / RPH) * NPXW;
    constexpr int SP   = TPW + 4;

    __shared__ __align__(16) float s_in[CI * (TPH + 2) * SP];
    __shared__ __align__(16) float s_w[CI * OCT * 12];

    const int tiles_w = W / TPW;
    const int ty0 = (blockIdx.x / tiles_w) * TPH;
    const int tx0 = (blockIdx.x % tiles_w) * TPW;
    const int b   = blockIdx.z;

    const int tid = threadIdx.x;
    const int pix = tid % NPX;
    const int ch  = tid / NPX;
    const int ly  = (pix / NPXW) * RPH;
    const int lx  = (pix % NPXW) * RPW;
    const int oc  = ch * RC;

    float acc[RC][RPH][RPW];
#pragma unroll
    for (int c = 0; c < RC; c++)
#pragma unroll
        for (int yy = 0; yy < RPH; yy++)
#pragma unroll
            for (int xx = 0; xx < RPW; xx++) acc[c][yy][xx] = 0.f;

    {
        constexpr int INEL = CI * (TPH + 2) * (TPW + 2);
        for (int idx = tid; idx < INEL; idx += 256) {
            int t = idx;
            const int ix = t % (TPW + 2); t /= (TPW + 2);
            const int iy = t % (TPH + 2); t /= (TPH + 2);
            const int ic = t;
            const int gy = ty0 + iy - 1, gx = tx0 + ix - 1;
            float v = 0.f;
            if (gy >= 0 && gy < H && gx >= 0 && gx < W)
                v = in[(((size_t)b * CI + ic) * H + gy) * W + gx];
            s_in[(ic * (TPH + 2) + iy) * SP + ix] = v;
        }
        for (int idx = tid; idx < CI * OCT * 9; idx += 256) {
            int t = idx;
            const int tt = t % 9;  t /= 9;
            const int ic = t % CI; t /= CI;
            const int o  = t;
            s_w[(ic * OCT + o) * 12 + tt] = wt[((size_t)o * CI + ic) * 9 + tt];
        }
        __syncthreads();

#pragma unroll
        for (int ic = 0; ic < CI; ic++) {
            const float* sbase = &s_in[(ic * (TPH + 2)) * SP];
            float wv[RC][9];
#pragma unroll
            for (int c = 0; c < RC; c++) {
                const float4* wp = (const float4*)&s_w[(ic * OCT + ch * RC + c) * 12];
                float4 w0 = wp[0], w1 = wp[1], w2 = wp[2];
                wv[c][0] = w0.x; wv[c][1] = w0.y; wv[c][2] = w0.z;
                wv[c][3] = w0.w; wv[c][4] = w1.x; wv[c][5] = w1.y;
                wv[c][6] = w1.z; wv[c][7] = w1.w; wv[c][8] = w2.x;
            }
            float r[3][8];
            {
                float4 u = *(const float4*)(sbase + (ly + 0) * SP + lx);
                float4 v = *(const float4*)(sbase + (ly + 0) * SP + lx + 4);
                r[0][0]=u.x;r[0][1]=u.y;r[0][2]=u.z;r[0][3]=u.w;r[0][4]=v.x;r[0][5]=v.y;r[0][6]=v.z;r[0][7]=v.w;
                u = *(const float4*)(sbase + (ly + 1) * SP + lx);
                v = *(const float4*)(sbase + (ly + 1) * SP + lx + 4);
                r[1][0]=u.x;r[1][1]=u.y;r[1][2]=u.z;r[1][3]=u.w;r[1][4]=v.x;r[1][5]=v.y;r[1][6]=v.z;r[1][7]=v.w;
            }
#pragma unroll
            for (int yy = 0; yy < RPH; yy++) {
                {
                    int rr = (yy + 2) % 3;
                    float4 u = *(const float4*)(sbase + (ly + yy + 2) * SP + lx);
                    float4 v = *(const float4*)(sbase + (ly + yy + 2) * SP + lx + 4);
                    r[rr][0]=u.x;r[rr][1]=u.y;r[rr][2]=u.z;r[rr][3]=u.w;r[rr][4]=v.x;r[rr][5]=v.y;r[rr][6]=v.z;r[rr][7]=v.w;
                }
                const int i0 = yy % 3, i1 = (yy + 1) % 3, i2 = (yy + 2) % 3;
#pragma unroll
                for (int c = 0; c < RC; c++)
#pragma unroll
                    for (int xx = 0; xx < RPW; xx++) {
                        float a = acc[c][yy][xx];
                        a = fmaf(wv[c][0], r[i0][xx],     a);
                        a = fmaf(wv[c][1], r[i0][xx + 1], a);
                        a = fmaf(wv[c][2], r[i0][xx + 2], a);
                        a = fmaf(wv[c][3], r[i1][xx],     a);
                        a = fmaf(wv[c][4], r[i1][xx + 1], a);
                        a = fmaf(wv[c][5], r[i1][xx + 2], a);
                        a = fmaf(wv[c][6], r[i2][xx],     a);
                        a = fmaf(wv[c][7], r[i2][xx + 1], a);
                        a = fmaf(wv[c][8], r[i2][xx + 2], a);
                        acc[c][yy][xx] = a;
                    }
            }
        }
    }

#pragma unroll
    for (int p = 0; p < RC / 2; p++) {
        const float bv0 = bias[oc + 2 * p];
        const float bv1 = bias[oc + 2 * p + 1];
#pragma unroll
        for (int y2 = 0; y2 < RPH / 2; y2++)
#pragma unroll
            for (int x2 = 0; x2 < RPW / 2; x2++) {
                int c0 = 2 * p, c1 = 2 * p + 1;
                float a0 = fmaxf(fmaxf(acc[c0][2*y2][2*x2], acc[c0][2*y2][2*x2+1]),
                                 fmaxf(acc[c0][2*y2+1][2*x2], acc[c0][2*y2+1][2*x2+1]));
                float a1 = fmaxf(fmaxf(acc[c1][2*y2][2*x2], acc[c1][2*y2][2*x2+1]),
                                 fmaxf(acc[c1][2*y2+1][2*x2], acc[c1][2*y2+1][2*x2+1]));
                float v0 = fmaxf(a0 + bv0, 0.f);
                float v1 = fmaxf(a1 + bv1, 0.f);
                float h0 = __bfloat162float(__float2bfloat16(v0));
                float h1 = __bfloat162float(__float2bfloat16(v1));
                int py = (ty0 + ly) / 2 + y2, px = (tx0 + lx) / 2 + x2;
                size_t w = ((size_t)b * 32 + (oc >> 1) + p) * (34 * 34)
                         + (size_t)(py + 1) * 34 + (px + 1);
                uint2 o; o.x = packbf2(h0, h1); o.y = packbf2(v0 - h0, v1 - h1);
                outT[w] = o;
            }
    }
}

// ---------------------------------------------------------------------------
// 2x2 maxpool fp32 NCHW -> packed interleaved padded tensor
// ---------------------------------------------------------------------------
__global__ void pool_split_p(const float* __restrict__ in, uint2* __restrict__ outT,
                             int total, int C, int H, int W)
{
    int i = blockIdx.x * blockDim.x + threadIdx.x;
    if (i >= total) return;                      // total = B*(C/2)*HO*WO
    int WO = W >> 1, HO = H >> 1;
    int x = i % WO;
    int t = i / WO;
    int y = t % HO; t /= HO;
    int pc = t % (C / 2);
    int b = t / (C / 2);
    const float* p0 = in + ((size_t)(b * C + 2 * pc) * H + 2 * y) * W + 2 * x;
    const float* p1 = p0 + (size_t)H * W;
    float v0 = fmaxf(fmaxf(p0[0], p0[1]), fmaxf(p0[W], p0[W + 1]));
    float v1 = fmaxf(fmaxf(p1[0], p1[1]), fmaxf(p1[W], p1[W + 1]));
    float h0 = __bfloat162float(__float2bfloat16(v0));
    float h1 = __bfloat162float(__float2bfloat16(v1));
    size_t w = ((size_t)(b * (C / 2) + pc)) * (size_t)((HO + 2) * (WO + 2))
             + (size_t)(y + 1) * (WO + 2) + (x + 1);
    uint2 o; o.x = packbf2(h0, h1); o.y = packbf2(v0 - h0, v1 - h1);
    outT[w] = o;
}

// ---------------------------------------------------------------------------
// Engram mask + final 2x2 pool + flatten to [B, 2048].
// ---------------------------------------------------------------------------
__global__ void mask_pool_flatten(const float* __restrict__ h,
                                  const int* __restrict__ y,
                                  const int* __restrict__ b_table,
                                  float* __restrict__ out)
{
    int b = blockIdx.x;
    __shared__ int ids[128];
    int t = threadIdx.x;
    if (t < 128) ids[t] = b_table[y[b] * 128 + t];
    __syncthreads();
    int c = t;
    bool on = false;
#pragma unroll 16
    for (int j = 0; j < 128; j++) on |= (ids[j] == c);
    float m = on ? 1.f : 0.f;
    const float* p = h + ((size_t)(b * 512 + c) * 16);
#pragma unroll
    for (int py = 0; py < 2; py++)
#pragma unroll
        for (int px = 0; px < 2; px++) {
            const float* q = p + (2 * py) * 4 + 2 * px;
            float v = fmaxf(fmaxf(q[0], q[1]), fmaxf(q[4], q[5]));
            out[(size_t)b * 2048 + c * 4 + py * 2 + px] = v * m;
        }
}

// ---------------------------------------------------------------------------
// FC layers (fp32).
// ---------------------------------------------------------------------------
template <bool RELU>
__global__ void __launch_bounds__(256)
fc_v2(const float* __restrict__ A, const float* __restrict__ W,
      const float* __restrict__ bias, float* __restrict__ C,
      int N, int K, int Klen)
{
    __shared__ __align__(16) float sA[16 * 68];
    __shared__ __align__(16) float sB[16 * 34];
    const int n0 = blockIdx.x * 32;
    const int k0base = blockIdx.y * Klen;
    float* Cp = C + (size_t)blockIdx.y * 64 * N;
    const int tid = threadIdx.x;
    const int tm = (tid / 16) * 4;
    const int tn = (tid % 16) * 2;
    float acc[4][2] = {};

    for (int k0 = k0base; k0 < k0base + Klen; k0 += 16) {
        __syncthreads();
        for (int i = tid; i < 64 * 16; i += 256) {
            int r = i / 16, kk = i % 16;
            sA[kk * 68 + r] = A[(size_t)r * K + k0 + kk];
        }
        for (int i = tid; i < 32 * 16; i += 256) {
            int cidx = i / 16, kk = i % 16;
            int col = n0 + cidx;
            sB[kk * 34 + cidx] = (col < N) ? W[(size_t)col * K + k0 + kk] : 0.f;
        }
        __syncthreads();
#pragma unroll
        for (int kk = 0; kk < 16; kk++) {
            float4 a = *(const float4*)&sA[kk * 68 + tm];
            float2 b = *(const float2*)&sB[kk * 34 + tn];
            acc[0][0] = fmaf(a.x, b.x, acc[0][0]);
            acc[0][1] = fmaf(a.x, b.y, acc[0][1]);
            acc[1][0] = fmaf(a.y, b.x, acc[1][0]);
            acc[1][1] = fmaf(a.y, b.y, acc[1][1]);
            acc[2][0] = fmaf(a.z, b.x, acc[2][0]);
            acc[2][1] = fmaf(a.z, b.y, acc[2][1]);
            acc[3][0] = fmaf(a.w, b.x, acc[3][0]);
            acc[3][1] = fmaf(a.w, b.y, acc[3][1]);
        }
    }
#pragma unroll
    for (int j = 0; j < 2; j++) {
        int col = n0 + tn + j;
        if (col >= N) continue;
        float bv = bias ? bias[col] : 0.f;
#pragma unroll
        for (int i = 0; i < 4; i++) {
            float v = acc[i][j] + bv;
            if (RELU) v = fmaxf(v, 0.f);
            Cp[(size_t)(tm + i) * N + col] = v;
        }
    }
}

__global__ void fc3_combine(const float* __restrict__ part,
                            const float* __restrict__ bias,
                            float* __restrict__ out, int N, int total)
{
    int i = blockIdx.x * blockDim.x + threadIdx.x;
    if (i >= total) return;
    int n = i % N;
    out[i] = part[i] + part[64 * N + i] + part[2 * 64 * N + i]
           + part[3 * 64 * N + i] + bias[n];
}

// ---------------------------------------------------------------------------
// Launch
// ---------------------------------------------------------------------------
extern "C" void kernel_launch(void* const* d_in, const int* in_sizes, int n_in,
                              void* d_out, int out_size)
{
    const float* x    = (const float*)d_in[0];
    const int*   y    = (const int*)d_in[1];
    const int*   bt   = (const int*)d_in[2];
    const float* cw0  = (const float*)d_in[3];
    const float* cb0  = (const float*)d_in[4];
    const float* cw1  = (const float*)d_in[5];
    const float* cb1  = (const float*)d_in[6];
    const float* cw2a = (const float*)d_in[7];
    const float* cb2a = (const float*)d_in[8];
    const float* cw2b = (const float*)d_in[9];
    const float* cb2b = (const float*)d_in[10];
    const float* cw3a = (const float*)d_in[11];
    const float* cb3a = (const float*)d_in[12];
    const float* cw3b = (const float*)d_in[13];
    const float* cb3b = (const float*)d_in[14];
    const float* cw4a = (const float*)d_in[15];
    const float* cb4a = (const float*)d_in[16];
    const float* cw4b = (const float*)d_in[17];
    const float* cb4b = (const float*)d_in[18];
    const float* fw1  = (const float*)d_in[19];
    const float* fb1  = (const float*)d_in[20];
    const float* fw2  = (const float*)d_in[21];
    const float* fb2  = (const float*)d_in[22];
    const float* fw3  = (const float*)d_in[23];
    const float* fb3  = (const float*)d_in[24];

    float* A;  float* Bp;
    uint2 *T1,*T2,*T3,*T4,*T5,*T6,*T7;
    uint32_t *WH, *WM;
    cudaGetSymbolAddress((void**)&A, g_A);
    cudaGetSymbolAddress((void**)&Bp, g_B);
    cudaGetSymbolAddress((void**)&T1, gT1);
    cudaGetSymbolAddress((void**)&T2, gT2);
    cudaGetSymbolAddress((void**)&T3, gT3);
    cudaGetSymbolAddress((void**)&T4, gT4);
    cudaGetSymbolAddress((void**)&T5, gT5);
    cudaGetSymbolAddress((void**)&T6, gT6);
    cudaGetSymbolAddress((void**)&T7, gT7);
    cudaGetSymbolAddress((void**)&WH, g_WH);
    cudaGetSymbolAddress((void**)&WM, g_WM);

    prep_w_all<<<(4608000 + 255) / 256, 256>>>(cw1, cw2a, cw2b, cw3a, cw3b, cw4a, cw4b);
    conv0_k<<<dim3(16, 1, 64), 256>>>(x, cw0, cb0, T1);

    // conv1 64->128 @32x32 -> Bp fp32; pool -> T2
    {
        auto k = conv_bf16<32, 32, 64, 128, 1, 8, false>;
        constexpr int SIN2 = 8 * 340;
        size_t sm = (size_t)SIN2 * 16 + 9216 * 4;
        cudaFuncSetAttribute(k, cudaFuncAttributeMaxDynamicSharedMemorySize, (int)sm);
        k<<<dim3(4, 4, 64), 256, sm>>>(T1, WH + WOFF_C1, WM + WOFF_C1, cb1, Bp, nullptr);
        int total = 64 * 64 * 16 * 16;
        pool_split_p<<<(total + 255)/256, 256>>>(Bp, T2, total, 128, 32, 32);
    }
    // conv2a 128->256 @16x16 -> T3 split
    {
        auto k = conv_bf16<16, 16, 128, 256, 1, 16, true>;
        constexpr int SIN2 = 8 * 324;
        size_t sm = (size_t)SIN2 * 16 + 9216 * 4;
        cudaFuncSetAttribute(k, cudaFuncAttributeMaxDynamicSharedMemorySize, (int)sm);
        k<<<dim3(1, 8, 64), 256, sm>>>(T2, WH + WOFF_C2A, WM + WOFF_C2A, cb2a, nullptr, T3);
    }
    // conv2b 256->256 @16x16 -> Bp fp32; pool -> T4
    {
        auto k = conv_bf16<16, 16, 256, 256, 1, 16, false>;
        constexpr int SIN2 = 8 * 324;
        size_t sm = (size_t)SIN2 * 16 + 9216 * 4;
        cudaFuncSetAttribute(k, cudaFuncAttributeMaxDynamicSharedMemorySize, (int)sm);
        k<<<dim3(1, 8, 64), 256, sm>>>(T3, WH + WOFF_C2B, WM + WOFF_C2B, cb2b, Bp, nullptr);
        int total = 64 * 128 * 8 * 8;
        pool_split_p<<<(total + 255)/256, 256>>>(Bp, T4, total, 256, 16, 16);
    }
    // conv3a 256->512 @8x8 (NB=2) -> T5 split
    {
        auto k = conv_bf16<8, 8, 256, 512, 2, 8, true>;
        constexpr int SIN2 = 2 * 8 * 100;
        size_t sm = (size_t)SIN2 * 16 + 9216 * 4;
        cudaFuncSetAttribute(k, cudaFuncAttributeMaxDynamicSharedMemorySize, (int)sm);
        k<<<dim3(1, 16, 32), 256, sm>>>(T4, WH + WOFF_C3A, WM + WOFF_C3A, cb3a, nullptr, T5);
    }
    // conv3b 512->512 @8x8 -> Bp fp32; pool -> T6
    {
        auto k = conv_bf16<8, 8, 512, 512, 2, 8, false>;
        constexpr int SIN2 = 2 * 8 * 100;
        size_t sm = (size_t)SIN2 * 16 + 9216 * 4;
        cudaFuncSetAttribute(k, cudaFuncAttributeMaxDynamicSharedMemorySize, (int)sm);
        k<<<dim3(1, 16, 32), 256, sm>>>(T5, WH + WOFF_C3B, WM + WOFF_C3B, cb3b, Bp, nullptr);
        int total = 64 * 256 * 4 * 4;
        pool_split_p<<<(total + 255)/256, 256>>>(Bp, T6, total, 512, 8, 8);
    }
    // conv4a 512->512 @4x4 (NB=4) -> T7 split
    {
        auto k = conv_bf16<4, 4, 512, 512, 4, 4, true>;
        constexpr int SIN2 = 4 * 8 * 36;
        size_t sm = (size_t)SIN2 * 16 + 9216 * 4;
        cudaFuncSetAttribute(k, cudaFuncAttributeMaxDynamicSharedMemorySize, (int)sm);
        k<<<dim3(1, 16, 16), 256, sm>>>(T6, WH + WOFF_C4A, WM + WOFF_C4A, cb4a, nullptr, T7);
    }
    // conv4b 512->512 @4x4 -> Bp fp32
    {
        auto k = conv_bf16<4, 4, 512, 512, 4, 4, false>;
        constexpr int SIN2 = 4 * 8 * 36;
        size_t sm = (size_t)SIN2 * 16 + 9216 * 4;
        cudaFuncSetAttribute(k, cudaFuncAttributeMaxDynamicSharedMemorySize, (int)sm);
        k<<<dim3(1, 16, 16), 256, sm>>>(T7, WH + WOFF_C4B, WM + WOFF_C4B, cb4b, Bp, nullptr);
    }

    // engram mask + pool -> flatten [64, 2048] -> A
    mask_pool_flatten<<<64, 512>>>(Bp, y, bt, A);

    // classifier
    fc_v2<true><<<dim3(128, 1), 256>>>(A, fw1, fb1, Bp, 4096, 2048, 2048);
    fc_v2<true><<<dim3(128, 1), 256>>>(Bp, fw2, fb2, A, 4096, 4096, 4096);
    fc_v2<false><<<dim3(32, 4), 256>>>(A, fw3, nullptr, Bp, 1000, 4096, 1024);
    fc3_combine<<<(64000 + 255)/256, 256>>>(Bp, fb3, (float*)d_out, 1000, 64000);
}

// round 16
// speedup vs baseline: 1.3582x; 1.3582x over previous
#include <cuda_runtime.h>
#include <cuda_bf16.h>
#include <stdint.h>
#include <math.h>

// ---------------------------------------------------------------------------
// Scratch. __device__ globals zero-init; halo rings never written -> stay 0.
// Activations: bf16 channel-pair packed, h (hi) and m (residual) arrays,
// layout [B][C/2][(H+2)*(W+2)] uint32 (lo16 = even channel).
// ---------------------------------------------------------------------------
__device__ float g_A[64 * 64 * 64 * 64];   // fp32 scratch
__device__ float g_B[64 * 128 * 32 * 32];  // fp32 scratch

__device__ uint32_t gS1h[64 * 32  * 34 * 34], gS1m[64 * 32  * 34 * 34];
__device__ uint32_t gS2h[64 * 64  * 18 * 18], gS2m[64 * 64  * 18 * 18];
__device__ uint32_t gS3h[64 * 128 * 18 * 18], gS3m[64 * 128 * 18 * 18];
__device__ uint32_t gS4h[64 * 128 * 10 * 10], gS4m[64 * 128 * 10 * 10];
__device__ uint32_t gS5h[64 * 256 * 10 * 10], gS5m[64 * 256 * 10 * 10];
__device__ uint32_t gS6h[64 * 256 * 6 * 6],   gS6m[64 * 256 * 6 * 6];
__device__ uint32_t gS7h[64 * 256 * 6 * 6],   gS7m[64 * 256 * 6 * 6];

// Weights: ldmatrix-ready layout, h and m separate arrays.
// per (cogrp, slice, kj): 256 words = 2 mt * 4 mats * (8 rows * 4 words)
__device__ uint32_t g_WH[4608000], g_WM[4608000];
#define WOFF_C1  0
#define WOFF_C2A 36864
#define WOFF_C2B 184320
#define WOFF_C3A 479232
#define WOFF_C3B 1069056
#define WOFF_C4A 2248704
#define WOFF_C4B 3428352

// ---------------------------------------------------------------------------
// helpers
// ---------------------------------------------------------------------------
__device__ __forceinline__ uint32_t packbf2(float lo, float hi) {
    uint32_t r;
    asm("cvt.rn.bf16x2.f32 %0, %1, %2;" : "=r"(r) : "f"(hi), "f"(lo));
    return r;
}
__device__ __forceinline__ void mma_bf16(float* d,
                                         uint32_t a0, uint32_t a1, uint32_t a2, uint32_t a3,
                                         uint32_t b0, uint32_t b1) {
    asm volatile(
        "mma.sync.aligned.m16n8k16.row.col.f32.bf16.bf16.f32 "
        "{%0,%1,%2,%3}, {%4,%5,%6,%7}, {%8,%9}, {%0,%1,%2,%3};"
        : "+f"(d[0]), "+f"(d[1]), "+f"(d[2]), "+f"(d[3])
        : "r"(a0), "r"(a1), "r"(a2), "r"(a3), "r"(b0), "r"(b1));
}
__device__ __forceinline__ void ldsm_x4(uint32_t* r, uint32_t addr) {
    asm volatile("ldmatrix.sync.aligned.m8n8.x4.shared.b16 {%0,%1,%2,%3}, [%4];"
        : "=r"(r[0]), "=r"(r[1]), "=r"(r[2]), "=r"(r[3]) : "r"(addr));
}
__device__ __forceinline__ void cp16(uint32_t dst, const void* src) {
    asm volatile("cp.async.cg.shared.global [%0], [%1], 16;" :: "r"(dst), "l"(src));
}

// ---------------------------------------------------------------------------
// Weight prep: fp32 OIHW -> ldmatrix-layout h/m arrays.
// word = ((cogrp*NSL + sl)*9 + kj)*256 + mt*128 + mat*32 + (m%8)*4 + (pc&3)
// ---------------------------------------------------------------------------
__global__ void prep_w_all(const float* __restrict__ w1, const float* __restrict__ w2a,
                           const float* __restrict__ w2b, const float* __restrict__ w3a,
                           const float* __restrict__ w3b, const float* __restrict__ w4a,
                           const float* __restrict__ w4b)
{
    int i = blockIdx.x * blockDim.x + threadIdx.x;
    const float* src; int CI; int woffl; int base;
    if      (i < 36864)   { src = w1;  CI = 64;  woffl = WOFF_C1;  base = 0; }
    else if (i < 184320)  { src = w2a; CI = 128; woffl = WOFF_C2A; base = 36864; }
    else if (i < 479232)  { src = w2b; CI = 256; woffl = WOFF_C2B; base = 184320; }
    else if (i < 1069056) { src = w3a; CI = 256; woffl = WOFF_C3A; base = 479232; }
    else if (i < 2248704) { src = w3b; CI = 512; woffl = WOFF_C3B; base = 1069056; }
    else if (i < 3428352) { src = w4a; CI = 512; woffl = WOFF_C4A; base = 2248704; }
    else if (i < 4608000) { src = w4b; CI = 512; woffl = WOFF_C4B; base = 3428352; }
    else return;
    int j  = i - base;
    int seg = (CI / 2) * 9;
    int co = j / seg;
    int r  = j % seg;
    int pcg = r / 9, kj = r % 9;
    int sl = pcg >> 3, pc = pcg & 7;
    float v0 = src[((size_t)co * CI + 2 * pcg) * 9 + kj];
    float v1 = src[((size_t)co * CI + 2 * pcg + 1) * 9 + kj];
    float h0 = __bfloat162float(__float2bfloat16(v0));
    float h1 = __bfloat162float(__float2bfloat16(v1));
    int mt = (co >> 4) & 1, m = co & 15;
    int mat = (pc < 4) ? ((m < 8) ? 0 : 1) : ((m < 8) ? 2 : 3);
    int NSL = CI / 16;
    size_t word = (size_t)woffl
                + ((((size_t)(co >> 5) * NSL + sl) * 9 + kj) * 256)
                + mt * 128 + mat * 32 + (m & 7) * 4 + (pc & 3);
    g_WH[word] = packbf2(h0, h1);
    g_WM[word] = packbf2(v0 - h0, v1 - h1);
}

// ---------------------------------------------------------------------------
// Implicit-GEMM conv3x3 SAME + bias + ReLU via bf16x2 (3-product) mma k16.
// 256 thr = 8 N-warps; CO tile 32 (2 m16/warp); 16 channels per K-slice.
// A-frags via ldmatrix.x4 (conflict-free); B via LDS.32 on separate h/m
// arrays with strides ≡8 mod 32 (conflict-free). cp.async 2-stage.
// ---------------------------------------------------------------------------
template <int H, int W, int CI, int CO, int NB, int NROW, int SLS, bool OUT_SPLIT>
__global__ void __launch_bounds__(256, 2)
conv_bf16(const uint32_t* __restrict__ inH, const uint32_t* __restrict__ inM,
          const uint32_t* __restrict__ wH,  const uint32_t* __restrict__ wM,
          const float* __restrict__ bias, float* __restrict__ outF,
          __nv_bfloat16* __restrict__ outH, __nv_bfloat16* __restrict__ outM)
{
    constexpr int WP = W + 2, HP = H + 2;
    constexpr int SP2 = W + 2;
    constexpr int GP = HP * WP;                 // global plane (words)
    constexpr int PLANE = (NROW + 2) * SP2;     // staged plane (words)
    constexpr int BN = NB * NROW * W;
    constexpr int WN = BN / 8;
    constexpr int NC = WN / 8;
    constexpr int SIN = NB * 8 * SLS;           // u32 per input buffer (h or m)
    constexpr int NCHI = PLANE / 4;
    constexpr int TCHI = NB * 8 * NCHI;
    constexpr int NSLICE = CI / 16;

    extern __shared__ uint32_t smu[];
    uint32_t* sInH[2] = { smu,            smu + SIN };
    uint32_t* sInM[2] = { smu + 2 * SIN,  smu + 3 * SIN };
    uint32_t* wbuf = smu + 4 * SIN;             // H0,H1,M0,M1 x 2304 words

    const int tid = threadIdx.x, warp = tid >> 5, lane = tid & 31;
    const int kk = lane & 3, ng = lane >> 2, wn = warp;
    const int ty0 = blockIdx.x * NROW;
    const int oc0 = blockIdx.y * 32;
    const int b0  = blockIdx.z * NB;

    const uint32_t wS = (uint32_t)__cvta_generic_to_shared(wbuf);
    const uint32_t wHS[2] = { wS, wS + 2304 * 4 };
    const uint32_t wMS[2] = { wS + 4608 * 4, wS + 6912 * 4 };

    int boff[NC];
#pragma unroll
    for (int ch = 0; ch < NC; ch++) {
        int n = wn * WN + ch * 8 + ng;
        int x = n % W; int t = n / W;
        int yy = t % NROW; int im = t / NROW;
        boff[ch] = (im * 8 + kk) * SLS + yy * SP2 + x;
    }

    float acc[2][NC][4];
#pragma unroll
    for (int mt = 0; mt < 2; mt++)
#pragma unroll
        for (int ch = 0; ch < NC; ch++)
#pragma unroll
            for (int j = 0; j < 4; j++) acc[mt][ch][j] = 0.f;

    auto stage = [&](int sl, int bufi) {
        uint32_t dH = (uint32_t)__cvta_generic_to_shared(sInH[bufi]);
        uint32_t dM = (uint32_t)__cvta_generic_to_shared(sInM[bufi]);
        for (int i = tid; i < TCHI; i += 256) {
            int c = i % NCHI; int t = i / NCHI;
            int pc = t % 8; int im = t / 8;
            size_t gbase = ((size_t)(b0 + im) * (CI / 2) + sl * 8 + pc) * GP
                         + (size_t)ty0 * WP + 4 * c;
            uint32_t soff = (uint32_t)(((im * 8 + pc) * SLS + 4 * c) * 4);
            cp16(dH + soff, inH + gbase);
            cp16(dM + soff, inM + gbase);
        }
        size_t wbase = ((size_t)blockIdx.y * NSLICE + sl) * 2304;
        uint32_t dWH = wHS[bufi], dWM = wMS[bufi];
        for (int i = tid; i < 576; i += 256) {
            cp16(dWH + (uint32_t)(i * 16), wH + wbase + 4 * i);
            cp16(dWM + (uint32_t)(i * 16), wM + wbase + 4 * i);
        }
        asm volatile("cp.async.commit_group;" ::: "memory");
    };

    stage(0, 0);
    for (int s = 0; s < NSLICE; s++) {
        if (s + 1 < NSLICE) {
            stage(s + 1, (s + 1) & 1);
            asm volatile("cp.async.wait_group 1;" ::: "memory");
        } else {
            asm volatile("cp.async.wait_group 0;" ::: "memory");
        }
        __syncthreads();

        const uint32_t* siH = sInH[s & 1];
        const uint32_t* siM = sInM[s & 1];
        const uint32_t aHb = wHS[s & 1] + lane * 16;
        const uint32_t aMb = wMS[s & 1] + lane * 16;
#pragma unroll 1
        for (int kj = 0; kj < 9; kj++) {
            const int kyx = (kj / 3) * SP2 + (kj % 3);
            uint32_t ah[2][4], am[2][4];
            ldsm_x4(ah[0], aHb + kj * 1024);
            ldsm_x4(ah[1], aHb + kj * 1024 + 512);
            ldsm_x4(am[0], aMb + kj * 1024);
            ldsm_x4(am[1], aMb + kj * 1024 + 512);

            uint32_t bh[NC][2], bm[NC][2];
#pragma unroll
            for (int ch = 0; ch < NC; ch++) {
                bh[ch][0] = siH[boff[ch] + kyx];
                bh[ch][1] = siH[boff[ch] + kyx + 4 * SLS];
                bm[ch][0] = siM[boff[ch] + kyx];
                bm[ch][1] = siM[boff[ch] + kyx + 4 * SLS];
            }
            // pass 1: h*h
#pragma unroll
            for (int ch = 0; ch < NC; ch++)
#pragma unroll
                for (int mt = 0; mt < 2; mt++)
                    mma_bf16(acc[mt][ch], ah[mt][0], ah[mt][1], ah[mt][2], ah[mt][3],
                             bh[ch][0], bh[ch][1]);
            // pass 2: h_w * m_x
#pragma unroll
            for (int ch = 0; ch < NC; ch++)
#pragma unroll
                for (int mt = 0; mt < 2; mt++)
                    mma_bf16(acc[mt][ch], ah[mt][0], ah[mt][1], ah[mt][2], ah[mt][3],
                             bm[ch][0], bm[ch][1]);
            // pass 3: m_w * h_x
#pragma unroll
            for (int ch = 0; ch < NC; ch++)
#pragma unroll
                for (int mt = 0; mt < 2; mt++)
                    mma_bf16(acc[mt][ch], am[mt][0], am[mt][1], am[mt][2], am[mt][3],
                             bh[ch][0], bh[ch][1]);
        }
        __syncthreads();
    }

    // epilogue
#pragma unroll
    for (int mt = 0; mt < 2; mt++) {
        const int co = oc0 + mt * 16 + ng;
        const float bva = bias[co];
        const float bvb = bias[co + 8];
#pragma unroll
        for (int ch = 0; ch < NC; ch++) {
#pragma unroll
            for (int j = 0; j < 2; j++) {
                int n = wn * WN + ch * 8 + kk * 2 + j;
                int x = n % W; int t = n / W;
                int yy = t % NROW; int im = t / NROW;
                float v0 = fmaxf(acc[mt][ch][j] + bva, 0.f);
                float v1 = fmaxf(acc[mt][ch][j + 2] + bvb, 0.f);
                if constexpr (OUT_SPLIT) {
                    size_t w0 = ((size_t)(b0 + im) * (CO / 2) + (co >> 1)) * GP
                              + (size_t)(ty0 + yy + 1) * WP + (x + 1);
                    size_t i0 = w0 * 2 + (co & 1);
                    __nv_bfloat16 hb0 = __float2bfloat16(v0);
                    outH[i0] = hb0;
                    outM[i0] = __float2bfloat16(v0 - __bfloat162float(hb0));
                    int co1 = co + 8;
                    size_t w1 = ((size_t)(b0 + im) * (CO / 2) + (co1 >> 1)) * GP
                              + (size_t)(ty0 + yy + 1) * WP + (x + 1);
                    size_t i1 = w1 * 2 + (co1 & 1);
                    __nv_bfloat16 hb1 = __float2bfloat16(v1);
                    outH[i1] = hb1;
                    outM[i1] = __float2bfloat16(v1 - __bfloat162float(hb1));
                } else {
                    size_t base = (((size_t)(b0 + im) * CO + co) * H + (ty0 + yy)) * W + x;
                    outF[base] = v0;
                    outF[base + (size_t)8 * H * W] = v1;
                }
            }
        }
    }
}

// ---------------------------------------------------------------------------
// conv0: direct fp32 3->64 @64x64, fused pool, writes packed S1 h/m.
// ---------------------------------------------------------------------------
__global__ void __launch_bounds__(256)
conv0_k(const float* __restrict__ in, const float* __restrict__ wt,
        const float* __restrict__ bias, uint32_t* __restrict__ outHp,
        uint32_t* __restrict__ outMp)
{
    constexpr int H = 64, W = 64, CI = 3, CO = 64;
    constexpr int TPH = 16, TPW = 16, RPH = 4, RPW = 4, OCT = 64, RC = 4;
    constexpr int NPXW = TPW / RPW;
    constexpr int NPX  = (TPH / RPH) * NPXW;
    constexpr int SP   = TPW + 4;

    __shared__ __align__(16) float s_in[CI * (TPH + 2) * SP];
    __shared__ __align__(16) float s_w[CI * OCT * 12];

    const int tiles_w = W / TPW;
    const int ty0 = (blockIdx.x / tiles_w) * TPH;
    const int tx0 = (blockIdx.x % tiles_w) * TPW;
    const int b   = blockIdx.z;

    const int tid = threadIdx.x;
    const int pix = tid % NPX;
    const int ch  = tid / NPX;
    const int ly  = (pix / NPXW) * RPH;
    const int lx  = (pix % NPXW) * RPW;
    const int oc  = ch * RC;

    float acc[RC][RPH][RPW];
#pragma unroll
    for (int c = 0; c < RC; c++)
#pragma unroll
        for (int yy = 0; yy < RPH; yy++)
#pragma unroll
            for (int xx = 0; xx < RPW; xx++) acc[c][yy][xx] = 0.f;

    {
        constexpr int INEL = CI * (TPH + 2) * (TPW + 2);
        for (int idx = tid; idx < INEL; idx += 256) {
            int t = idx;
            const int ix = t % (TPW + 2); t /= (TPW + 2);
            const int iy = t % (TPH + 2); t /= (TPH + 2);
            const int ic = t;
            const int gy = ty0 + iy - 1, gx = tx0 + ix - 1;
            float v = 0.f;
            if (gy >= 0 && gy < H && gx >= 0 && gx < W)
                v = in[(((size_t)b * CI + ic) * H + gy) * W + gx];
            s_in[(ic * (TPH + 2) + iy) * SP + ix] = v;
        }
        for (int idx = tid; idx < CI * OCT * 9; idx += 256) {
            int t = idx;
            const int tt = t % 9;  t /= 9;
            const int ic = t % CI; t /= CI;
            const int o  = t;
            s_w[(ic * OCT + o) * 12 + tt] = wt[((size_t)o * CI + ic) * 9 + tt];
        }
        __syncthreads();

#pragma unroll
        for (int ic = 0; ic < CI; ic++) {
            const float* sbase = &s_in[(ic * (TPH + 2)) * SP];
            float wv[RC][9];
#pragma unroll
            for (int c = 0; c < RC; c++) {
                const float4* wp = (const float4*)&s_w[(ic * OCT + ch * RC + c) * 12];
                float4 w0 = wp[0], w1 = wp[1], w2 = wp[2];
                wv[c][0] = w0.x; wv[c][1] = w0.y; wv[c][2] = w0.z;
                wv[c][3] = w0.w; wv[c][4] = w1.x; wv[c][5] = w1.y;
                wv[c][6] = w1.z; wv[c][7] = w1.w; wv[c][8] = w2.x;
            }
            float r[3][8];
            {
                float4 u = *(const float4*)(sbase + (ly + 0) * SP + lx);
                float4 v = *(const float4*)(sbase + (ly + 0) * SP + lx + 4);
                r[0][0]=u.x;r[0][1]=u.y;r[0][2]=u.z;r[0][3]=u.w;r[0][4]=v.x;r[0][5]=v.y;r[0][6]=v.z;r[0][7]=v.w;
                u = *(const float4*)(sbase + (ly + 1) * SP + lx);
                v = *(const float4*)(sbase + (ly + 1) * SP + lx + 4);
                r[1][0]=u.x;r[1][1]=u.y;r[1][2]=u.z;r[1][3]=u.w;r[1][4]=v.x;r[1][5]=v.y;r[1][6]=v.z;r[1][7]=v.w;
            }
#pragma unroll
            for (int yy = 0; yy < RPH; yy++) {
                {
                    int rr = (yy + 2) % 3;
                    float4 u = *(const float4*)(sbase + (ly + yy + 2) * SP + lx);
                    float4 v = *(const float4*)(sbase + (ly + yy + 2) * SP + lx + 4);
                    r[rr][0]=u.x;r[rr][1]=u.y;r[rr][2]=u.z;r[rr][3]=u.w;r[rr][4]=v.x;r[rr][5]=v.y;r[rr][6]=v.z;r[rr][7]=v.w;
                }
                const int i0 = yy % 3, i1 = (yy + 1) % 3, i2 = (yy + 2) % 3;
#pragma unroll
                for (int c = 0; c < RC; c++)
#pragma unroll
                    for (int xx = 0; xx < RPW; xx++) {
                        float a = acc[c][yy][xx];
                        a = fmaf(wv[c][0], r[i0][xx],     a);
                        a = fmaf(wv[c][1], r[i0][xx + 1], a);
                        a = fmaf(wv[c][2], r[i0][xx + 2], a);
                        a = fmaf(wv[c][3], r[i1][xx],     a);
                        a = fmaf(wv[c][4], r[i1][xx + 1], a);
                        a = fmaf(wv[c][5], r[i1][xx + 2], a);
                        a = fmaf(wv[c][6], r[i2][xx],     a);
                        a = fmaf(wv[c][7], r[i2][xx + 1], a);
                        a = fmaf(wv[c][8], r[i2][xx + 2], a);
                        acc[c][yy][xx] = a;
                    }
            }
        }
    }

#pragma unroll
    for (int p = 0; p < RC / 2; p++) {
        const float bv0 = bias[oc + 2 * p];
        const float bv1 = bias[oc + 2 * p + 1];
#pragma unroll
        for (int y2 = 0; y2 < RPH / 2; y2++)
#pragma unroll
            for (int x2 = 0; x2 < RPW / 2; x2++) {
                int c0 = 2 * p, c1 = 2 * p + 1;
                float a0 = fmaxf(fmaxf(acc[c0][2*y2][2*x2], acc[c0][2*y2][2*x2+1]),
                                 fmaxf(acc[c0][2*y2+1][2*x2], acc[c0][2*y2+1][2*x2+1]));
                float a1 = fmaxf(fmaxf(acc[c1][2*y2][2*x2], acc[c1][2*y2][2*x2+1]),
                                 fmaxf(acc[c1][2*y2+1][2*x2], acc[c1][2*y2+1][2*x2+1]));
                float v0 = fmaxf(a0 + bv0, 0.f);
                float v1 = fmaxf(a1 + bv1, 0.f);
                float h0 = __bfloat162float(__float2bfloat16(v0));
                float h1 = __bfloat162float(__float2bfloat16(v1));
                int py = (ty0 + ly) / 2 + y2, px = (tx0 + lx) / 2 + x2;
                size_t w = ((size_t)b * 32 + (oc >> 1) + p) * (34 * 34)
                         + (size_t)(py + 1) * 34 + (px + 1);
                outHp[w] = packbf2(h0, h1);
                outMp[w] = packbf2(v0 - h0, v1 - h1);
            }
    }
}

// ---------------------------------------------------------------------------
// 2x2 maxpool fp32 NCHW -> packed split padded pair tensor
// ---------------------------------------------------------------------------
__global__ void pool_split_p(const float* __restrict__ in, uint32_t* __restrict__ outh,
                             uint32_t* __restrict__ outm, int total, int C, int H, int W)
{
    int i = blockIdx.x * blockDim.x + threadIdx.x;
    if (i >= total) return;                      // total = B*(C/2)*HO*WO
    int WO = W >> 1, HO = H >> 1;
    int x = i % WO;
    int t = i / WO;
    int y = t % HO; t /= HO;
    int pc = t % (C / 2);
    int b = t / (C / 2);
    const float* p0 = in + ((size_t)(b * C + 2 * pc) * H + 2 * y) * W + 2 * x;
    const float* p1 = p0 + (size_t)H * W;
    float v0 = fmaxf(fmaxf(p0[0], p0[1]), fmaxf(p0[W], p0[W + 1]));
    float v1 = fmaxf(fmaxf(p1[0], p1[1]), fmaxf(p1[W], p1[W + 1]));
    float h0 = __bfloat162float(__float2bfloat16(v0));
    float h1 = __bfloat162float(__float2bfloat16(v1));
    size_t w = ((size_t)(b * (C / 2) + pc)) * (size_t)((HO + 2) * (WO + 2))
             + (size_t)(y + 1) * (WO + 2) + (x + 1);
    outh[w] = packbf2(h0, h1);
    outm[w] = packbf2(v0 - h0, v1 - h1);
}

// ---------------------------------------------------------------------------
// Engram mask + final 2x2 pool + flatten to [B, 2048].
// ---------------------------------------------------------------------------
__global__ void mask_pool_flatten(const float* __restrict__ h,
                                  const int* __restrict__ y,
                                  const int* __restrict__ b_table,
                                  float* __restrict__ out)
{
    int b = blockIdx.x;
    __shared__ int ids[128];
    int t = threadIdx.x;
    if (t < 128) ids[t] = b_table[y[b] * 128 + t];
    __syncthreads();
    int c = t;
    bool on = false;
#pragma unroll 16
    for (int j = 0; j < 128; j++) on |= (ids[j] == c);
    float m = on ? 1.f : 0.f;
    const float* p = h + ((size_t)(b * 512 + c) * 16);
#pragma unroll
    for (int py = 0; py < 2; py++)
#pragma unroll
        for (int px = 0; px < 2; px++) {
            const float* q = p + (2 * py) * 4 + 2 * px;
            float v = fmaxf(fmaxf(q[0], q[1]), fmaxf(q[4], q[5]));
            out[(size_t)b * 2048 + c * 4 + py * 2 + px] = v * m;
        }
}

// ---------------------------------------------------------------------------
// FC layers (fp32).
// ---------------------------------------------------------------------------
template <bool RELU>
__global__ void __launch_bounds__(256)
fc_v2(const float* __restrict__ A, const float* __restrict__ W,
      const float* __restrict__ bias, float* __restrict__ C,
      int N, int K, int Klen)
{
    __shared__ __align__(16) float sA[16 * 68];
    __shared__ __align__(16) float sB[16 * 34];
    const int n0 = blockIdx.x * 32;
    const int k0base = blockIdx.y * Klen;
    float* Cp = C + (size_t)blockIdx.y * 64 * N;
    const int tid = threadIdx.x;
    const int tm = (tid / 16) * 4;
    const int tn = (tid % 16) * 2;
    float acc[4][2] = {};

    for (int k0 = k0base; k0 < k0base + Klen; k0 += 16) {
        __syncthreads();
        for (int i = tid; i < 64 * 16; i += 256) {
            int r = i / 16, kk = i % 16;
            sA[kk * 68 + r] = A[(size_t)r * K + k0 + kk];
        }
        for (int i = tid; i < 32 * 16; i += 256) {
            int cidx = i / 16, kk = i % 16;
            int col = n0 + cidx;
            sB[kk * 34 + cidx] = (col < N) ? W[(size_t)col * K + k0 + kk] : 0.f;
        }
        __syncthreads();
#pragma unroll
        for (int kk = 0; kk < 16; kk++) {
            float4 a = *(const float4*)&sA[kk * 68 + tm];
            float2 b = *(const float2*)&sB[kk * 34 + tn];
            acc[0][0] = fmaf(a.x, b.x, acc[0][0]);
            acc[0][1] = fmaf(a.x, b.y, acc[0][1]);
            acc[1][0] = fmaf(a.y, b.x, acc[1][0]);
            acc[1][1] = fmaf(a.y, b.y, acc[1][1]);
            acc[2][0] = fmaf(a.z, b.x, acc[2][0]);
            acc[2][1] = fmaf(a.z, b.y, acc[2][1]);
            acc[3][0] = fmaf(a.w, b.x, acc[3][0]);
            acc[3][1] = fmaf(a.w, b.y, acc[3][1]);
        }
    }
#pragma unroll
    for (int j = 0; j < 2; j++) {
        int col = n0 + tn + j;
        if (col >= N) continue;
        float bv = bias ? bias[col] : 0.f;
#pragma unroll
        for (int i = 0; i < 4; i++) {
            float v = acc[i][j] + bv;
            if (RELU) v = fmaxf(v, 0.f);
            Cp[(size_t)(tm + i) * N + col] = v;
        }
    }
}

__global__ void fc3_combine(const float* __restrict__ part,
                            const float* __restrict__ bias,
                            float* __restrict__ out, int N, int total)
{
    int i = blockIdx.x * blockDim.x + threadIdx.x;
    if (i >= total) return;
    int n = i % N;
    out[i] = part[i] + part[64 * N + i] + part[2 * 64 * N + i]
           + part[3 * 64 * N + i] + bias[n];
}

// ---------------------------------------------------------------------------
// Launch
// ---------------------------------------------------------------------------
extern "C" void kernel_launch(void* const* d_in, const int* in_sizes, int n_in,
                              void* d_out, int out_size)
{
    const float* x    = (const float*)d_in[0];
    const int*   y    = (const int*)d_in[1];
    const int*   bt   = (const int*)d_in[2];
    const float* cw0  = (const float*)d_in[3];
    const float* cb0  = (const float*)d_in[4];
    const float* cw1  = (const float*)d_in[5];
    const float* cb1  = (const float*)d_in[6];
    const float* cw2a = (const float*)d_in[7];
    const float* cb2a = (const float*)d_in[8];
    const float* cw2b = (const float*)d_in[9];
    const float* cb2b = (const float*)d_in[10];
    const float* cw3a = (const float*)d_in[11];
    const float* cb3a = (const float*)d_in[12];
    const float* cw3b = (const float*)d_in[13];
    const float* cb3b = (const float*)d_in[14];
    const float* cw4a = (const float*)d_in[15];
    const float* cb4a = (const float*)d_in[16];
    const float* cw4b = (const float*)d_in[17];
    const float* cb4b = (const float*)d_in[18];
    const float* fw1  = (const float*)d_in[19];
    const float* fb1  = (const float*)d_in[20];
    const float* fw2  = (const float*)d_in[21];
    const float* fb2  = (const float*)d_in[22];
    const float* fw3  = (const float*)d_in[23];
    const float* fb3  = (const float*)d_in[24];

    float* A;  float* Bp;
    uint32_t *S1h,*S1m,*S2h,*S2m,*S3h,*S3m,*S4h,*S4m,*S5h,*S5m,*S6h,*S6m,*S7h,*S7m;
    uint32_t *WH, *WM;
    cudaGetSymbolAddress((void**)&A, g_A);
    cudaGetSymbolAddress((void**)&Bp, g_B);
    cudaGetSymbolAddress((void**)&S1h, gS1h); cudaGetSymbolAddress((void**)&S1m, gS1m);
    cudaGetSymbolAddress((void**)&S2h, gS2h); cudaGetSymbolAddress((void**)&S2m, gS2m);
    cudaGetSymbolAddress((void**)&S3h, gS3h); cudaGetSymbolAddress((void**)&S3m, gS3m);
    cudaGetSymbolAddress((void**)&S4h, gS4h); cudaGetSymbolAddress((void**)&S4m, gS4m);
    cudaGetSymbolAddress((void**)&S5h, gS5h); cudaGetSymbolAddress((void**)&S5m, gS5m);
    cudaGetSymbolAddress((void**)&S6h, gS6h); cudaGetSymbolAddress((void**)&S6m, gS6m);
    cudaGetSymbolAddress((void**)&S7h, gS7h); cudaGetSymbolAddress((void**)&S7m, gS7m);
    cudaGetSymbolAddress((void**)&WH, g_WH);  cudaGetSymbolAddress((void**)&WM, g_WM);

    prep_w_all<<<(4608000 + 255) / 256, 256>>>(cw1, cw2a, cw2b, cw3a, cw3b, cw4a, cw4b);
    conv0_k<<<dim3(16, 1, 64), 256>>>(x, cw0, cb0, S1h, S1m);

    // conv1 64->128 @32x32 -> Bp fp32; pool -> S2
    {
        auto k = conv_bf16<32, 32, 64, 128, 1, 8, 360, false>;
        constexpr int SIN = 8 * 360;
        size_t sm = (size_t)(4 * SIN + 9216) * 4;
        cudaFuncSetAttribute(k, cudaFuncAttributeMaxDynamicSharedMemorySize, (int)sm);
        k<<<dim3(4, 4, 64), 256, sm>>>(S1h, S1m, WH + WOFF_C1, WM + WOFF_C1,
                                       cb1, Bp, nullptr, nullptr);
        int total = 64 * 64 * 16 * 16;
        pool_split_p<<<(total + 255)/256, 256>>>(Bp, S2h, S2m, total, 128, 32, 32);
    }
    // conv2a 128->256 @16x16 -> S3 split
    {
        auto k = conv_bf16<16, 16, 128, 256, 1, 16, 328, true>;
        constexpr int SIN = 8 * 328;
        size_t sm = (size_t)(4 * SIN + 9216) * 4;
        cudaFuncSetAttribute(k, cudaFuncAttributeMaxDynamicSharedMemorySize, (int)sm);
        k<<<dim3(1, 8, 64), 256, sm>>>(S2h, S2m, WH + WOFF_C2A, WM + WOFF_C2A,
                                       cb2a, nullptr,
                                       (__nv_bfloat16*)S3h, (__nv_bfloat16*)S3m);
    }
    // conv2b 256->256 @16x16 -> Bp fp32; pool -> S4
    {
        auto k = conv_bf16<16, 16, 256, 256, 1, 16, 328, false>;
        constexpr int SIN = 8 * 328;
        size_t sm = (size_t)(4 * SIN + 9216) * 4;
        cudaFuncSetAttribute(k, cudaFuncAttributeMaxDynamicSharedMemorySize, (int)sm);
        k<<<dim3(1, 8, 64), 256, sm>>>(S3h, S3m, WH + WOFF_C2B, WM + WOFF_C2B,
                                       cb2b, Bp, nullptr, nullptr);
        int total = 64 * 128 * 8 * 8;
        pool_split_p<<<(total + 255)/256, 256>>>(Bp, S4h, S4m, total, 256, 16, 16);
    }
    // conv3a 256->512 @8x8 (NB=2) -> S5 split
    {
        auto k = conv_bf16<8, 8, 256, 512, 2, 8, 104, true>;
        constexpr int SIN = 2 * 8 * 104;
        size_t sm = (size_t)(4 * SIN + 9216) * 4;
        cudaFuncSetAttribute(k, cudaFuncAttributeMaxDynamicSharedMemorySize, (int)sm);
        k<<<dim3(1, 16, 32), 256, sm>>>(S4h, S4m, WH + WOFF_C3A, WM + WOFF_C3A,
                                        cb3a, nullptr,
                                        (__nv_bfloat16*)S5h, (__nv_bfloat16*)S5m);
    }
    // conv3b 512->512 @8x8 -> Bp fp32; pool -> S6
    {
        auto k = conv_bf16<8, 8, 512, 512, 2, 8, 104, false>;
        constexpr int SIN = 2 * 8 * 104;
        size_t sm = (size_t)(4 * SIN + 9216) * 4;
        cudaFuncSetAttribute(k, cudaFuncAttributeMaxDynamicSharedMemorySize, (int)sm);
        k<<<dim3(1, 16, 32), 256, sm>>>(S5h, S5m, WH + WOFF_C3B, WM + WOFF_C3B,
                                        cb3b, Bp, nullptr, nullptr);
        int total = 64 * 256 * 4 * 4;
        pool_split_p<<<(total + 255)/256, 256>>>(Bp, S6h, S6m, total, 512, 8, 8);
    }
    // conv4a 512->512 @4x4 (NB=4) -> S7 split
    {
        auto k = conv_bf16<4, 4, 512, 512, 4, 4, 40, true>;
        constexpr int SIN = 4 * 8 * 40;
        size_t sm = (size_t)(4 * SIN + 9216) * 4;
        cudaFuncSetAttribute(k, cudaFuncAttributeMaxDynamicSharedMemorySize, (int)sm);
        k<<<dim3(1, 16, 16), 256, sm>>>(S6h, S6m, WH + WOFF_C4A, WM + WOFF_C4A,
                                        cb4a, nullptr,
                                        (__nv_bfloat16*)S7h, (__nv_bfloat16*)S7m);
    }
    // conv4b 512->512 @4x4 -> Bp fp32
    {
        auto k = conv_bf16<4, 4, 512, 512, 4, 4, 40, false>;
        constexpr int SIN = 4 * 8 * 40;
        size_t sm = (size_t)(4 * SIN + 9216) * 4;
        cudaFuncSetAttribute(k, cudaFuncAttributeMaxDynamicSharedMemorySize, (int)sm);
        k<<<dim3(1, 16, 16), 256, sm>>>(S7h, S7m, WH + WOFF_C4B, WM + WOFF_C4B,
                                        cb4b, Bp, nullptr, nullptr);
    }

    // engram mask + pool -> flatten [64, 2048] -> A
    mask_pool_flatten<<<64, 512>>>(Bp, y, bt, A);

    // classifier
    fc_v2<true><<<dim3(128, 1), 256>>>(A, fw1, fb1, Bp, 4096, 2048, 2048);
    fc_v2<true><<<dim3(128, 1), 256>>>(Bp, fw2, fb2, A, 4096, 4096, 4096);
    fc_v2<false><<<dim3(32, 4), 256>>>(A, fw3, nullptr, Bp, 1000, 4096, 1024);
    fc3_combine<<<(64000 + 255)/256, 256>>>(Bp, fb3, (float*)d_out, 1000, 64000);
}

// round 17
// speedup vs baseline: 1.4355x; 1.0569x over previous
#include <cuda_runtime.h>
#include <cuda_bf16.h>
#include <stdint.h>
#include <math.h>

// ---------------------------------------------------------------------------
// Scratch. __device__ globals zero-init; halo rings never written -> stay 0.
// Activations: bf16 channel-pair packed, h (hi) and m (residual) arrays,
// layout [B][C/2][(H+2)*(W+2)] uint32 (lo16 = even channel).
// ---------------------------------------------------------------------------
__device__ float g_A[64 * 64 * 64 * 64];   // fp32 scratch
__device__ float g_B[64 * 128 * 32 * 32];  // fp32 scratch

__device__ uint32_t gS1h[64 * 32  * 34 * 34], gS1m[64 * 32  * 34 * 34];
__device__ uint32_t gS2h[64 * 64  * 18 * 18], gS2m[64 * 64  * 18 * 18];
__device__ uint32_t gS3h[64 * 128 * 18 * 18], gS3m[64 * 128 * 18 * 18];
__device__ uint32_t gS4h[64 * 128 * 10 * 10], gS4m[64 * 128 * 10 * 10];
__device__ uint32_t gS5h[64 * 256 * 10 * 10], gS5m[64 * 256 * 10 * 10];
__device__ uint32_t gS6h[64 * 256 * 6 * 6],   gS6m[64 * 256 * 6 * 6];
__device__ uint32_t gS7h[64 * 256 * 6 * 6],   gS7m[64 * 256 * 6 * 6];

// Weights: ldmatrix-ready layout, h and m separate arrays.
// per (cogrp, slice, kj): 256 words = 2 mt * 4 mats * (8 rows * 4 words)
__device__ uint32_t g_WH[4608000], g_WM[4608000];
#define WOFF_C1  0
#define WOFF_C2A 36864
#define WOFF_C2B 184320
#define WOFF_C3A 479232
#define WOFF_C3B 1069056
#define WOFF_C4A 2248704
#define WOFF_C4B 3428352

// ---------------------------------------------------------------------------
// helpers
// ---------------------------------------------------------------------------
__device__ __forceinline__ uint32_t packbf2(float lo, float hi) {
    uint32_t r;
    asm("cvt.rn.bf16x2.f32 %0, %1, %2;" : "=r"(r) : "f"(hi), "f"(lo));
    return r;
}
__device__ __forceinline__ void mma_bf16(float* d,
                                         uint32_t a0, uint32_t a1, uint32_t a2, uint32_t a3,
                                         uint32_t b0, uint32_t b1) {
    asm volatile(
        "mma.sync.aligned.m16n8k16.row.col.f32.bf16.bf16.f32 "
        "{%0,%1,%2,%3}, {%4,%5,%6,%7}, {%8,%9}, {%0,%1,%2,%3};"
        : "+f"(d[0]), "+f"(d[1]), "+f"(d[2]), "+f"(d[3])
        : "r"(a0), "r"(a1), "r"(a2), "r"(a3), "r"(b0), "r"(b1));
}
__device__ __forceinline__ void ldsm_x4(uint32_t* r, uint32_t addr) {
    asm volatile("ldmatrix.sync.aligned.m8n8.x4.shared.b16 {%0,%1,%2,%3}, [%4];"
        : "=r"(r[0]), "=r"(r[1]), "=r"(r[2]), "=r"(r[3]) : "r"(addr));
}
__device__ __forceinline__ void cp16(uint32_t dst, const void* src) {
    asm volatile("cp.async.cg.shared.global [%0], [%1], 16;" :: "r"(dst), "l"(src));
}

// ---------------------------------------------------------------------------
// Weight prep: fp32 OIHW -> ldmatrix-layout h/m arrays.
// word = ((cogrp*NSL + sl)*9 + kj)*256 + mt*128 + mat*32 + (m%8)*4 + (pc&3)
// ---------------------------------------------------------------------------
__global__ void prep_w_all(const float* __restrict__ w1, const float* __restrict__ w2a,
                           const float* __restrict__ w2b, const float* __restrict__ w3a,
                           const float* __restrict__ w3b, const float* __restrict__ w4a,
                           const float* __restrict__ w4b)
{
    int i = blockIdx.x * blockDim.x + threadIdx.x;
    const float* src; int CI; int woffl; int base;
    if      (i < 36864)   { src = w1;  CI = 64;  woffl = WOFF_C1;  base = 0; }
    else if (i < 184320)  { src = w2a; CI = 128; woffl = WOFF_C2A; base = 36864; }
    else if (i < 479232)  { src = w2b; CI = 256; woffl = WOFF_C2B; base = 184320; }
    else if (i < 1069056) { src = w3a; CI = 256; woffl = WOFF_C3A; base = 479232; }
    else if (i < 2248704) { src = w3b; CI = 512; woffl = WOFF_C3B; base = 1069056; }
    else if (i < 3428352) { src = w4a; CI = 512; woffl = WOFF_C4A; base = 2248704; }
    else if (i < 4608000) { src = w4b; CI = 512; woffl = WOFF_C4B; base = 3428352; }
    else return;
    int j  = i - base;
    int seg = (CI / 2) * 9;
    int co = j / seg;
    int r  = j % seg;
    int pcg = r / 9, kj = r % 9;
    int sl = pcg >> 3, pc = pcg & 7;
    float v0 = src[((size_t)co * CI + 2 * pcg) * 9 + kj];
    float v1 = src[((size_t)co * CI + 2 * pcg + 1) * 9 + kj];
    float h0 = __bfloat162float(__float2bfloat16(v0));
    float h1 = __bfloat162float(__float2bfloat16(v1));
    int mt = (co >> 4) & 1, m = co & 15;
    int mat = (pc < 4) ? ((m < 8) ? 0 : 1) : ((m < 8) ? 2 : 3);
    int NSL = CI / 16;
    size_t word = (size_t)woffl
                + ((((size_t)(co >> 5) * NSL + sl) * 9 + kj) * 256)
                + mt * 128 + mat * 32 + (m & 7) * 4 + (pc & 3);
    g_WH[word] = packbf2(h0, h1);
    g_WM[word] = packbf2(v0 - h0, v1 - h1);
}

// ---------------------------------------------------------------------------
// Implicit-GEMM conv3x3 SAME + bias + ReLU via bf16x2 (3-product) mma k16.
// 256 thr = 8 N-warps; CO tile 32 (2 m16/warp); 16 channels per K-slice.
// A via ldmatrix.x4, B via LDS.32 (conflict-free). Fragment loads
// software-pipelined one kj ahead (double-buffered registers, kj unrolled).
// ---------------------------------------------------------------------------
template <int H, int W, int CI, int CO, int NB, int NROW, int SLS, bool OUT_SPLIT>
__global__ void __launch_bounds__(256, 2)
conv_bf16(const uint32_t* __restrict__ inH, const uint32_t* __restrict__ inM,
          const uint32_t* __restrict__ wH,  const uint32_t* __restrict__ wM,
          const float* __restrict__ bias, float* __restrict__ outF,
          __nv_bfloat16* __restrict__ outH, __nv_bfloat16* __restrict__ outM)
{
    constexpr int WP = W + 2, HP = H + 2;
    constexpr int SP2 = W + 2;
    constexpr int GP = HP * WP;                 // global plane (words)
    constexpr int PLANE = (NROW + 2) * SP2;     // staged plane (words)
    constexpr int BN = NB * NROW * W;
    constexpr int WN = BN / 8;
    constexpr int NC = WN / 8;
    constexpr int SIN = NB * 8 * SLS;           // u32 per input buffer (h or m)
    constexpr int NCHI = PLANE / 4;
    constexpr int TCHI = NB * 8 * NCHI;
    constexpr int NSLICE = CI / 16;

    extern __shared__ uint32_t smu[];
    uint32_t* sInH[2] = { smu,            smu + SIN };
    uint32_t* sInM[2] = { smu + 2 * SIN,  smu + 3 * SIN };
    uint32_t* wbuf = smu + 4 * SIN;             // H0,H1,M0,M1 x 2304 words

    const int tid = threadIdx.x, warp = tid >> 5, lane = tid & 31;
    const int kk = lane & 3, ng = lane >> 2, wn = warp;
    const int ty0 = blockIdx.x * NROW;
    const int oc0 = blockIdx.y * 32;
    const int b0  = blockIdx.z * NB;

    const uint32_t wS = (uint32_t)__cvta_generic_to_shared(wbuf);
    const uint32_t wHS[2] = { wS, wS + 2304 * 4 };
    const uint32_t wMS[2] = { wS + 4608 * 4, wS + 6912 * 4 };

    int boff[NC];
#pragma unroll
    for (int ch = 0; ch < NC; ch++) {
        int n = wn * WN + ch * 8 + ng;
        int x = n % W; int t = n / W;
        int yy = t % NROW; int im = t / NROW;
        boff[ch] = (im * 8 + kk) * SLS + yy * SP2 + x;
    }

    float acc[2][NC][4];
#pragma unroll
    for (int mt = 0; mt < 2; mt++)
#pragma unroll
        for (int ch = 0; ch < NC; ch++)
#pragma unroll
            for (int j = 0; j < 4; j++) acc[mt][ch][j] = 0.f;

    auto stage = [&](int sl, int bufi) {
        uint32_t dH = (uint32_t)__cvta_generic_to_shared(sInH[bufi]);
        uint32_t dM = (uint32_t)__cvta_generic_to_shared(sInM[bufi]);
        for (int i = tid; i < TCHI; i += 256) {
            int c = i % NCHI; int t = i / NCHI;
            int pc = t % 8; int im = t / 8;
            size_t gbase = ((size_t)(b0 + im) * (CI / 2) + sl * 8 + pc) * GP
                         + (size_t)ty0 * WP + 4 * c;
            uint32_t soff = (uint32_t)(((im * 8 + pc) * SLS + 4 * c) * 4);
            cp16(dH + soff, inH + gbase);
            cp16(dM + soff, inM + gbase);
        }
        size_t wbase = ((size_t)blockIdx.y * NSLICE + sl) * 2304;
        uint32_t dWH = wHS[bufi], dWM = wMS[bufi];
        for (int i = tid; i < 576; i += 256) {
            cp16(dWH + (uint32_t)(i * 16), wH + wbase + 4 * i);
            cp16(dWM + (uint32_t)(i * 16), wM + wbase + 4 * i);
        }
        asm volatile("cp.async.commit_group;" ::: "memory");
    };

    stage(0, 0);
    for (int s = 0; s < NSLICE; s++) {
        if (s + 1 < NSLICE) {
            stage(s + 1, (s + 1) & 1);
            asm volatile("cp.async.wait_group 1;" ::: "memory");
        } else {
            asm volatile("cp.async.wait_group 0;" ::: "memory");
        }
        __syncthreads();

        const uint32_t* siH = sInH[s & 1];
        const uint32_t* siM = sInM[s & 1];
        const uint32_t aHb = wHS[s & 1] + lane * 16;
        const uint32_t aMb = wMS[s & 1] + lane * 16;

        // double-buffered fragment registers
        uint32_t ah[2][2][4], am[2][2][4];
        uint32_t bh[2][NC][2], bm[2][NC][2];

        // prologue: load kj=0 into buffer 0 (kyx = 0)
        ldsm_x4(ah[0][0], aHb);
        ldsm_x4(ah[0][1], aHb + 512);
        ldsm_x4(am[0][0], aMb);
        ldsm_x4(am[0][1], aMb + 512);
#pragma unroll
        for (int ch = 0; ch < NC; ch++) {
            bh[0][ch][0] = siH[boff[ch]];
            bh[0][ch][1] = siH[boff[ch] + 4 * SLS];
            bm[0][ch][0] = siM[boff[ch]];
            bm[0][ch][1] = siM[boff[ch] + 4 * SLS];
        }

#pragma unroll
        for (int kj = 0; kj < 9; kj++) {
            const int cur = kj & 1, nxt = cur ^ 1;
            if (kj < 8) {
                const int kn = kj + 1;
                const int kyx = (kn / 3) * SP2 + (kn % 3);
                ldsm_x4(ah[nxt][0], aHb + kn * 1024);
                ldsm_x4(ah[nxt][1], aHb + kn * 1024 + 512);
                ldsm_x4(am[nxt][0], aMb + kn * 1024);
                ldsm_x4(am[nxt][1], aMb + kn * 1024 + 512);
#pragma unroll
                for (int ch = 0; ch < NC; ch++) {
                    bh[nxt][ch][0] = siH[boff[ch] + kyx];
                    bh[nxt][ch][1] = siH[boff[ch] + kyx + 4 * SLS];
                    bm[nxt][ch][0] = siM[boff[ch] + kyx];
                    bm[nxt][ch][1] = siM[boff[ch] + kyx + 4 * SLS];
                }
            }
            // pass 1: h*h
#pragma unroll
            for (int ch = 0; ch < NC; ch++)
#pragma unroll
                for (int mt = 0; mt < 2; mt++)
                    mma_bf16(acc[mt][ch],
                             ah[cur][mt][0], ah[cur][mt][1], ah[cur][mt][2], ah[cur][mt][3],
                             bh[cur][ch][0], bh[cur][ch][1]);
            // pass 2: h_w * m_x
#pragma unroll
            for (int ch = 0; ch < NC; ch++)
#pragma unroll
                for (int mt = 0; mt < 2; mt++)
                    mma_bf16(acc[mt][ch],
                             ah[cur][mt][0], ah[cur][mt][1], ah[cur][mt][2], ah[cur][mt][3],
                             bm[cur][ch][0], bm[cur][ch][1]);
            // pass 3: m_w * h_x
#pragma unroll
            for (int ch = 0; ch < NC; ch++)
#pragma unroll
                for (int mt = 0; mt < 2; mt++)
                    mma_bf16(acc[mt][ch],
                             am[cur][mt][0], am[cur][mt][1], am[cur][mt][2], am[cur][mt][3],
                             bh[cur][ch][0], bh[cur][ch][1]);
        }
        __syncthreads();
    }

    // epilogue
#pragma unroll
    for (int mt = 0; mt < 2; mt++) {
        const int co = oc0 + mt * 16 + ng;
        const float bva = bias[co];
        const float bvb = bias[co + 8];
#pragma unroll
        for (int ch = 0; ch < NC; ch++) {
#pragma unroll
            for (int j = 0; j < 2; j++) {
                int n = wn * WN + ch * 8 + kk * 2 + j;
                int x = n % W; int t = n / W;
                int yy = t % NROW; int im = t / NROW;
                float v0 = fmaxf(acc[mt][ch][j] + bva, 0.f);
                float v1 = fmaxf(acc[mt][ch][j + 2] + bvb, 0.f);
                if constexpr (OUT_SPLIT) {
                    size_t w0 = ((size_t)(b0 + im) * (CO / 2) + (co >> 1)) * GP
                              + (size_t)(ty0 + yy + 1) * WP + (x + 1);
                    size_t i0 = w0 * 2 + (co & 1);
                    __nv_bfloat16 hb0 = __float2bfloat16(v0);
                    outH[i0] = hb0;
                    outM[i0] = __float2bfloat16(v0 - __bfloat162float(hb0));
                    int co1 = co + 8;
                    size_t w1 = ((size_t)(b0 + im) * (CO / 2) + (co1 >> 1)) * GP
                              + (size_t)(ty0 + yy + 1) * WP + (x + 1);
                    size_t i1 = w1 * 2 + (co1 & 1);
                    __nv_bfloat16 hb1 = __float2bfloat16(v1);
                    outH[i1] = hb1;
                    outM[i1] = __float2bfloat16(v1 - __bfloat162float(hb1));
                } else {
                    size_t base = (((size_t)(b0 + im) * CO + co) * H + (ty0 + yy)) * W + x;
                    outF[base] = v0;
                    outF[base + (size_t)8 * H * W] = v1;
                }
            }
        }
    }
}

// ---------------------------------------------------------------------------
// conv0: direct fp32 3->64 @64x64, fused pool, writes packed S1 h/m.
// ---------------------------------------------------------------------------
__global__ void __launch_bounds__(256)
conv0_k(const float* __restrict__ in, const float* __restrict__ wt,
        const float* __restrict__ bias, uint32_t* __restrict__ outHp,
        uint32_t* __restrict__ outMp)
{
    constexpr int H = 64, W = 64, CI = 3, CO = 64;
    constexpr int TPH = 16, TPW = 16, RPH = 4, RPW = 4, OCT = 64, RC = 4;
    constexpr int NPXW = TPW / RPW;
    constexpr int NPX  = (TPH / RPH) * NPXW;
    constexpr int SP   = TPW + 4;

    __shared__ __align__(16) float s_in[CI * (TPH + 2) * SP];
    __shared__ __align__(16) float s_w[CI * OCT * 12];

    const int tiles_w = W / TPW;
    const int ty0 = (blockIdx.x / tiles_w) * TPH;
    const int tx0 = (blockIdx.x % tiles_w) * TPW;
    const int b   = blockIdx.z;

    const int tid = threadIdx.x;
    const int pix = tid % NPX;
    const int ch  = tid / NPX;
    const int ly  = (pix / NPXW) * RPH;
    const int lx  = (pix % NPXW) * RPW;
    const int oc  = ch * RC;

    float acc[RC][RPH][RPW];
#pragma unroll
    for (int c = 0; c < RC; c++)
#pragma unroll
        for (int yy = 0; yy < RPH; yy++)
#pragma unroll
            for (int xx = 0; xx < RPW; xx++) acc[c][yy][xx] = 0.f;

    {
        constexpr int INEL = CI * (TPH + 2) * (TPW + 2);
        for (int idx = tid; idx < INEL; idx += 256) {
            int t = idx;
            const int ix = t % (TPW + 2); t /= (TPW + 2);
            const int iy = t % (TPH + 2); t /= (TPH + 2);
            const int ic = t;
            const int gy = ty0 + iy - 1, gx = tx0 + ix - 1;
            float v = 0.f;
            if (gy >= 0 && gy < H && gx >= 0 && gx < W)
                v = in[(((size_t)b * CI + ic) * H + gy) * W + gx];
            s_in[(ic * (TPH + 2) + iy) * SP + ix] = v;
        }
        for (int idx = tid; idx < CI * OCT * 9; idx += 256) {
            int t = idx;
            const int tt = t % 9;  t /= 9;
            const int ic = t % CI; t /= CI;
            const int o  = t;
            s_w[(ic * OCT + o) * 12 + tt] = wt[((size_t)o * CI + ic) * 9 + tt];
        }
        __syncthreads();

#pragma unroll
        for (int ic = 0; ic < CI; ic++) {
            const float* sbase = &s_in[(ic * (TPH + 2)) * SP];
            float wv[RC][9];
#pragma unroll
            for (int c = 0; c < RC; c++) {
                const float4* wp = (const float4*)&s_w[(ic * OCT + ch * RC + c) * 12];
                float4 w0 = wp[0], w1 = wp[1], w2 = wp[2];
                wv[c][0] = w0.x; wv[c][1] = w0.y; wv[c][2] = w0.z;
                wv[c][3] = w0.w; wv[c][4] = w1.x; wv[c][5] = w1.y;
                wv[c][6] = w1.z; wv[c][7] = w1.w; wv[c][8] = w2.x;
            }
            float r[3][8];
            {
                float4 u = *(const float4*)(sbase + (ly + 0) * SP + lx);
                float4 v = *(const float4*)(sbase + (ly + 0) * SP + lx + 4);
                r[0][0]=u.x;r[0][1]=u.y;r[0][2]=u.z;r[0][3]=u.w;r[0][4]=v.x;r[0][5]=v.y;r[0][6]=v.z;r[0][7]=v.w;
                u = *(const float4*)(sbase + (ly + 1) * SP + lx);
                v = *(const float4*)(sbase + (ly + 1) * SP + lx + 4);
                r[1][0]=u.x;r[1][1]=u.y;r[1][2]=u.z;r[1][3]=u.w;r[1][4]=v.x;r[1][5]=v.y;r[1][6]=v.z;r[1][7]=v.w;
            }
#pragma unroll
            for (int yy = 0; yy < RPH; yy++) {
                {
                    int rr = (yy + 2) % 3;
                    float4 u = *(const float4*)(sbase + (ly + yy + 2) * SP + lx);
                    float4 v = *(const float4*)(sbase + (ly + yy + 2) * SP + lx + 4);
                    r[rr][0]=u.x;r[rr][1]=u.y;r[rr][2]=u.z;r[rr][3]=u.w;r[rr][4]=v.x;r[rr][5]=v.y;r[rr][6]=v.z;r[rr][7]=v.w;
                }
                const int i0 = yy % 3, i1 = (yy + 1) % 3, i2 = (yy + 2) % 3;
#pragma unroll
                for (int c = 0; c < RC; c++)
#pragma unroll
                    for (int xx = 0; xx < RPW; xx++) {
                        float a = acc[c][yy][xx];
                        a = fmaf(wv[c][0], r[i0][xx],     a);
                        a = fmaf(wv[c][1], r[i0][xx + 1], a);
                        a = fmaf(wv[c][2], r[i0][xx + 2], a);
                        a = fmaf(wv[c][3], r[i1][xx],     a);
                        a = fmaf(wv[c][4], r[i1][xx + 1], a);
                        a = fmaf(wv[c][5], r[i1][xx + 2], a);
                        a = fmaf(wv[c][6], r[i2][xx],     a);
                        a = fmaf(wv[c][7], r[i2][xx + 1], a);
                        a = fmaf(wv[c][8], r[i2][xx + 2], a);
                        acc[c][yy][xx] = a;
                    }
            }
        }
    }

#pragma unroll
    for (int p = 0; p < RC / 2; p++) {
        const float bv0 = bias[oc + 2 * p];
        const float bv1 = bias[oc + 2 * p + 1];
#pragma unroll
        for (int y2 = 0; y2 < RPH / 2; y2++)
#pragma unroll
            for (int x2 = 0; x2 < RPW / 2; x2++) {
                int c0 = 2 * p, c1 = 2 * p + 1;
                float a0 = fmaxf(fmaxf(acc[c0][2*y2][2*x2], acc[c0][2*y2][2*x2+1]),
                                 fmaxf(acc[c0][2*y2+1][2*x2], acc[c0][2*y2+1][2*x2+1]));
                float a1 = fmaxf(fmaxf(acc[c1][2*y2][2*x2], acc[c1][2*y2][2*x2+1]),
                                 fmaxf(acc[c1][2*y2+1][2*x2], acc[c1][2*y2+1][2*x2+1]));
                float v0 = fmaxf(a0 + bv0, 0.f);
                float v1 = fmaxf(a1 + bv1, 0.f);
                float h0 = __bfloat162float(__float2bfloat16(v0));
                float h1 = __bfloat162float(__float2bfloat16(v1));
                int py = (ty0 + ly) / 2 + y2, px = (tx0 + lx) / 2 + x2;
                size_t w = ((size_t)b * 32 + (oc >> 1) + p) * (34 * 34)
                         + (size_t)(py + 1) * 34 + (px + 1);
                outHp[w] = packbf2(h0, h1);
                outMp[w] = packbf2(v0 - h0, v1 - h1);
            }
    }
}

// ---------------------------------------------------------------------------
// 2x2 maxpool fp32 NCHW -> packed split padded pair tensor
// ---------------------------------------------------------------------------
__global__ void pool_split_p(const float* __restrict__ in, uint32_t* __restrict__ outh,
                             uint32_t* __restrict__ outm, int total, int C, int H, int W)
{
    int i = blockIdx.x * blockDim.x + threadIdx.x;
    if (i >= total) return;                      // total = B*(C/2)*HO*WO
    int WO = W >> 1, HO = H >> 1;
    int x = i % WO;
    int t = i / WO;
    int y = t % HO; t /= HO;
    int pc = t % (C / 2);
    int b = t / (C / 2);
    const float* p0 = in + ((size_t)(b * C + 2 * pc) * H + 2 * y) * W + 2 * x;
    const float* p1 = p0 + (size_t)H * W;
    float v0 = fmaxf(fmaxf(p0[0], p0[1]), fmaxf(p0[W], p0[W + 1]));
    float v1 = fmaxf(fmaxf(p1[0], p1[1]), fmaxf(p1[W], p1[W + 1]));
    float h0 = __bfloat162float(__float2bfloat16(v0));
    float h1 = __bfloat162float(__float2bfloat16(v1));
    size_t w = ((size_t)(b * (C / 2) + pc)) * (size_t)((HO + 2) * (WO + 2))
             + (size_t)(y + 1) * (WO + 2) + (x + 1);
    outh[w] = packbf2(h0, h1);
    outm[w] = packbf2(v0 - h0, v1 - h1);
}

// ---------------------------------------------------------------------------
// Engram mask + final 2x2 pool + flatten to [B, 2048].
// ---------------------------------------------------------------------------
__global__ void mask_pool_flatten(const float* __restrict__ h,
                                  const int* __restrict__ y,
                                  const int* __restrict__ b_table,
                                  float* __restrict__ out)
{
    int b = blockIdx.x;
    __shared__ int ids[128];
    int t = threadIdx.x;
    if (t < 128) ids[t] = b_table[y[b] * 128 + t];
    __syncthreads();
    int c = t;
    bool on = false;
#pragma unroll 16
    for (int j = 0; j < 128; j++) on |= (ids[j] == c);
    float m = on ? 1.f : 0.f;
    const float* p = h + ((size_t)(b * 512 + c) * 16);
#pragma unroll
    for (int py = 0; py < 2; py++)
#pragma unroll
        for (int px = 0; px < 2; px++) {
            const float* q = p + (2 * py) * 4 + 2 * px;
            float v = fmaxf(fmaxf(q[0], q[1]), fmaxf(q[4], q[5]));
            out[(size_t)b * 2048 + c * 4 + py * 2 + px] = v * m;
        }
}

// ---------------------------------------------------------------------------
// FC layers (fp32).
// ---------------------------------------------------------------------------
template <bool RELU>
__global__ void __launch_bounds__(256)
fc_v2(const float* __restrict__ A, const float* __restrict__ W,
      const float* __restrict__ bias, float* __restrict__ C,
      int N, int K, int Klen)
{
    __shared__ __align__(16) float sA[16 * 68];
    __shared__ __align__(16) float sB[16 * 34];
    const int n0 = blockIdx.x * 32;
    const int k0base = blockIdx.y * Klen;
    float* Cp = C + (size_t)blockIdx.y * 64 * N;
    const int tid = threadIdx.x;
    const int tm = (tid / 16) * 4;
    const int tn = (tid % 16) * 2;
    float acc[4][2] = {};

    for (int k0 = k0base; k0 < k0base + Klen; k0 += 16) {
        __syncthreads();
        for (int i = tid; i < 64 * 16; i += 256) {
            int r = i / 16, kk = i % 16;
            sA[kk * 68 + r] = A[(size_t)r * K + k0 + kk];
        }
        for (int i = tid; i < 32 * 16; i += 256) {
            int cidx = i / 16, kk = i % 16;
            int col = n0 + cidx;
            sB[kk * 34 + cidx] = (col < N) ? W[(size_t)col * K + k0 + kk] : 0.f;
        }
        __syncthreads();
#pragma unroll
        for (int kk = 0; kk < 16; kk++) {
            float4 a = *(const float4*)&sA[kk * 68 + tm];
            float2 b = *(const float2*)&sB[kk * 34 + tn];
            acc[0][0] = fmaf(a.x, b.x, acc[0][0]);
            acc[0][1] = fmaf(a.x, b.y, acc[0][1]);
            acc[1][0] = fmaf(a.y, b.x, acc[1][0]);
            acc[1][1] = fmaf(a.y, b.y, acc[1][1]);
            acc[2][0] = fmaf(a.z, b.x, acc[2][0]);
            acc[2][1] = fmaf(a.z, b.y, acc[2][1]);
            acc[3][0] = fmaf(a.w, b.x, acc[3][0]);
            acc[3][1] = fmaf(a.w, b.y, acc[3][1]);
        }
    }
#pragma unroll
    for (int j = 0; j < 2; j++) {
        int col = n0 + tn + j;
        if (col >= N) continue;
        float bv = bias ? bias[col] : 0.f;
#pragma unroll
        for (int i = 0; i < 4; i++) {
            float v = acc[i][j] + bv;
            if (RELU) v = fmaxf(v, 0.f);
            Cp[(size_t)(tm + i) * N + col] = v;
        }
    }
}

__global__ void fc3_combine(const float* __restrict__ part,
                            const float* __restrict__ bias,
                            float* __restrict__ out, int N, int total)
{
    int i = blockIdx.x * blockDim.x + threadIdx.x;
    if (i >= total) return;
    int n = i % N;
    out[i] = part[i] + part[64 * N + i] + part[2 * 64 * N + i]
           + part[3 * 64 * N + i] + bias[n];
}

// ---------------------------------------------------------------------------
// Launch
// ---------------------------------------------------------------------------
extern "C" void kernel_launch(void* const* d_in, const int* in_sizes, int n_in,
                              void* d_out, int out_size)
{
    const float* x    = (const float*)d_in[0];
    const int*   y    = (const int*)d_in[1];
    const int*   bt   = (const int*)d_in[2];
    const float* cw0  = (const float*)d_in[3];
    const float* cb0  = (const float*)d_in[4];
    const float* cw1  = (const float*)d_in[5];
    const float* cb1  = (const float*)d_in[6];
    const float* cw2a = (const float*)d_in[7];
    const float* cb2a = (const float*)d_in[8];
    const float* cw2b = (const float*)d_in[9];
    const float* cb2b = (const float*)d_in[10];
    const float* cw3a = (const float*)d_in[11];
    const float* cb3a = (const float*)d_in[12];
    const float* cw3b = (const float*)d_in[13];
    const float* cb3b = (const float*)d_in[14];
    const float* cw4a = (const float*)d_in[15];
    const float* cb4a = (const float*)d_in[16];
    const float* cw4b = (const float*)d_in[17];
    const float* cb4b = (const float*)d_in[18];
    const float* fw1  = (const float*)d_in[19];
    const float* fb1  = (const float*)d_in[20];
    const float* fw2  = (const float*)d_in[21];
    const float* fb2  = (const float*)d_in[22];
    const float* fw3  = (const float*)d_in[23];
    const float* fb3  = (const float*)d_in[24];

    float* A;  float* Bp;
    uint32_t *S1h,*S1m,*S2h,*S2m,*S3h,*S3m,*S4h,*S4m,*S5h,*S5m,*S6h,*S6m,*S7h,*S7m;
    uint32_t *WH, *WM;
    cudaGetSymbolAddress((void**)&A, g_A);
    cudaGetSymbolAddress((void**)&Bp, g_B);
    cudaGetSymbolAddress((void**)&S1h, gS1h); cudaGetSymbolAddress((void**)&S1m, gS1m);
    cudaGetSymbolAddress((void**)&S2h, gS2h); cudaGetSymbolAddress((void**)&S2m, gS2m);
    cudaGetSymbolAddress((void**)&S3h, gS3h); cudaGetSymbolAddress((void**)&S3m, gS3m);
    cudaGetSymbolAddress((void**)&S4h, gS4h); cudaGetSymbolAddress((void**)&S4m, gS4m);
    cudaGetSymbolAddress((void**)&S5h, gS5h); cudaGetSymbolAddress((void**)&S5m, gS5m);
    cudaGetSymbolAddress((void**)&S6h, gS6h); cudaGetSymbolAddress((void**)&S6m, gS6m);
    cudaGetSymbolAddress((void**)&S7h, gS7h); cudaGetSymbolAddress((void**)&S7m, gS7m);
    cudaGetSymbolAddress((void**)&WH, g_WH);  cudaGetSymbolAddress((void**)&WM, g_WM);

    prep_w_all<<<(4608000 + 255) / 256, 256>>>(cw1, cw2a, cw2b, cw3a, cw3b, cw4a, cw4b);
    conv0_k<<<dim3(16, 1, 64), 256>>>(x, cw0, cb0, S1h, S1m);

    // conv1 64->128 @32x32 -> Bp fp32; pool -> S2
    {
        auto k = conv_bf16<32, 32, 64, 128, 1, 8, 360, false>;
        constexpr int SIN = 8 * 360;
        size_t sm = (size_t)(4 * SIN + 9216) * 4;
        cudaFuncSetAttribute(k, cudaFuncAttributeMaxDynamicSharedMemorySize, (int)sm);
        k<<<dim3(4, 4, 64), 256, sm>>>(S1h, S1m, WH + WOFF_C1, WM + WOFF_C1,
                                       cb1, Bp, nullptr, nullptr);
        int total = 64 * 64 * 16 * 16;
        pool_split_p<<<(total + 255)/256, 256>>>(Bp, S2h, S2m, total, 128, 32, 32);
    }
    // conv2a 128->256 @16x16 -> S3 split
    {
        auto k = conv_bf16<16, 16, 128, 256, 1, 16, 328, true>;
        constexpr int SIN = 8 * 328;
        size_t sm = (size_t)(4 * SIN + 9216) * 4;
        cudaFuncSetAttribute(k, cudaFuncAttributeMaxDynamicSharedMemorySize, (int)sm);
        k<<<dim3(1, 8, 64), 256, sm>>>(S2h, S2m, WH + WOFF_C2A, WM + WOFF_C2A,
                                       cb2a, nullptr,
                                       (__nv_bfloat16*)S3h, (__nv_bfloat16*)S3m);
    }
    // conv2b 256->256 @16x16 -> Bp fp32; pool -> S4
    {
        auto k = conv_bf16<16, 16, 256, 256, 1, 16, 328, false>;
        constexpr int SIN = 8 * 328;
        size_t sm = (size_t)(4 * SIN + 9216) * 4;
        cudaFuncSetAttribute(k, cudaFuncAttributeMaxDynamicSharedMemorySize, (int)sm);
        k<<<dim3(1, 8, 64), 256, sm>>>(S3h, S3m, WH + WOFF_C2B, WM + WOFF_C2B,
                                       cb2b, Bp, nullptr, nullptr);
        int total = 64 * 128 * 8 * 8;
        pool_split_p<<<(total + 255)/256, 256>>>(Bp, S4h, S4m, total, 256, 16, 16);
    }
    // conv3a 256->512 @8x8 (NB=2) -> S5 split
    {
        auto k = conv_bf16<8, 8, 256, 512, 2, 8, 104, true>;
        constexpr int SIN = 2 * 8 * 104;
        size_t sm = (size_t)(4 * SIN + 9216) * 4;
        cudaFuncSetAttribute(k, cudaFuncAttributeMaxDynamicSharedMemorySize, (int)sm);
        k<<<dim3(1, 16, 32), 256, sm>>>(S4h, S4m, WH + WOFF_C3A, WM + WOFF_C3A,
                                        cb3a, nullptr,
                                        (__nv_bfloat16*)S5h, (__nv_bfloat16*)S5m);
    }
    // conv3b 512->512 @8x8 -> Bp fp32; pool -> S6
    {
        auto k = conv_bf16<8, 8, 512, 512, 2, 8, 104, false>;
        constexpr int SIN = 2 * 8 * 104;
        size_t sm = (size_t)(4 * SIN + 9216) * 4;
        cudaFuncSetAttribute(k, cudaFuncAttributeMaxDynamicSharedMemorySize, (int)sm);
        k<<<dim3(1, 16, 32), 256, sm>>>(S5h, S5m, WH + WOFF_C3B, WM + WOFF_C3B,
                                        cb3b, Bp, nullptr, nullptr);
        int total = 64 * 256 * 4 * 4;
        pool_split_p<<<(total + 255)/256, 256>>>(Bp, S6h, S6m, total, 512, 8, 8);
    }
    // conv4a 512->512 @4x4 (NB=4) -> S7 split
    {
        auto k = conv_bf16<4, 4, 512, 512, 4, 4, 40, true>;
        constexpr int SIN = 4 * 8 * 40;
        size_t sm = (size_t)(4 * SIN + 9216) * 4;
        cudaFuncSetAttribute(k, cudaFuncAttributeMaxDynamicSharedMemorySize, (int)sm);
        k<<<dim3(1, 16, 16), 256, sm>>>(S6h, S6m, WH + WOFF_C4A, WM + WOFF_C4A,
                                        cb4a, nullptr,
                                        (__nv_bfloat16*)S7h, (__nv_bfloat16*)S7m);
    }
    // conv4b 512->512 @4x4 -> Bp fp32
    {
        auto k = conv_bf16<4, 4, 512, 512, 4, 4, 40, false>;
        constexpr int SIN = 4 * 8 * 40;
        size_t sm = (size_t)(4 * SIN + 9216) * 4;
        cudaFuncSetAttribute(k, cudaFuncAttributeMaxDynamicSharedMemorySize, (int)sm);
        k<<<dim3(1, 16, 16), 256, sm>>>(S7h, S7m, WH + WOFF_C4B, WM + WOFF_C4B,
                                        cb4b, Bp, nullptr, nullptr);
    }

    // engram mask + pool -> flatten [64, 2048] -> A
    mask_pool_flatten<<<64, 512>>>(Bp, y, bt, A);

    // classifier
    fc_v2<true><<<dim3(128, 1), 256>>>(A, fw1, fb1, Bp, 4096, 2048, 2048);
    fc_v2<true><<<dim3(128, 1), 256>>>(Bp, fw2, fb2, A, 4096, 4096, 4096);
    fc_v2<false><<<dim3(32, 4), 256>>>(A, fw3, nullptr, Bp, 1000, 4096, 1024);
    fc3_combine<<<(64000 + 255)/256, 256>>>(Bp, fb3, (float*)d_out, 1000, 64000);
}